// round 4
// baseline (speedup 1.0000x reference)
#include <cuda_runtime.h>
#include <cstddef>

// Problem constants
#define SS   4096
#define BB   8
#define DD   1024
#define HH   1024
#define N3   (3*HH)          // 3072
#define MM   (SS*BB)         // 32768
#define KK   DD              // 1024

// Scratch: device globals (no allocation allowed)
__device__ float g_gates[(size_t)MM * N3];   // 402 MB
__device__ float g_h1[(size_t)MM * HH];      // 134 MB

// ---------------------------------------------------------------------------
// GEMM: C[M,N] = A[M,K] * B[K,N] + bias[N]
// M=32768, N=3072, K=1024. fp32 SIMT, 128x128x16 tiles, 8x8 per thread,
// double-buffered smem, 1 syncthreads per k-tile.
// ---------------------------------------------------------------------------
#define BM 128
#define BN 128
#define BK 16
#define PAD 4

__global__ void __launch_bounds__(256, 2)
gemm_bias_kernel(const float* __restrict__ A, const float* __restrict__ Bm,
                 const float* __restrict__ bias, float* __restrict__ C)
{
    __shared__ float As[2][BK][BM + PAD];
    __shared__ float Bs[2][BK][BN + PAD];

    const int tid = threadIdx.x;
    const int bm = blockIdx.y * BM;
    const int bn = blockIdx.x * BN;

    // global-load mapping
    const int arow = tid >> 2;          // 0..63
    const int acol = (tid & 3) * 4;     // 0,4,8,12
    const int brow = tid >> 5;          // 0..7
    const int bcol = (tid & 31) * 4;    // 0..124

    // compute mapping
    const int ty = tid >> 4;            // 0..15
    const int tx = tid & 15;            // 0..15

    const float* Aptr0 = A + (size_t)(bm + arow) * KK + acol;
    const float* Aptr1 = A + (size_t)(bm + arow + 64) * KK + acol;
    const float* Bptr0 = Bm + (size_t)brow * N3 + bn + bcol;
    const float* Bptr1 = Bm + (size_t)(brow + 8) * N3 + bn + bcol;

    float4 ra0, ra1, rb0, rb1;          // prefetch registers
    float acc[8][8];
    #pragma unroll
    for (int i = 0; i < 8; ++i)
        #pragma unroll
        for (int j = 0; j < 8; ++j) acc[i][j] = 0.0f;

    const int NT = KK / BK;             // 64

    // prologue: tile 0 -> smem buf 0
    ra0 = *(const float4*)(Aptr0);
    ra1 = *(const float4*)(Aptr1);
    rb0 = *(const float4*)(Bptr0);
    rb1 = *(const float4*)(Bptr1);
    {
        As[0][acol + 0][arow] = ra0.x; As[0][acol + 1][arow] = ra0.y;
        As[0][acol + 2][arow] = ra0.z; As[0][acol + 3][arow] = ra0.w;
        As[0][acol + 0][arow + 64] = ra1.x; As[0][acol + 1][arow + 64] = ra1.y;
        As[0][acol + 2][arow + 64] = ra1.z; As[0][acol + 3][arow + 64] = ra1.w;
        *(float4*)&Bs[0][brow][bcol] = rb0;
        *(float4*)&Bs[0][brow + 8][bcol] = rb1;
    }
    __syncthreads();

    // prefetch tile 1
    ra0 = *(const float4*)(Aptr0 + BK);
    ra1 = *(const float4*)(Aptr1 + BK);
    rb0 = *(const float4*)(Bptr0 + (size_t)BK * N3);
    rb1 = *(const float4*)(Bptr1 + (size_t)BK * N3);

    for (int t = 0; t < NT; ++t) {
        const int cur = t & 1;
        // compute on buf cur
        #pragma unroll
        for (int kk = 0; kk < BK; ++kk) {
            float4 a0 = *(const float4*)&As[cur][kk][ty * 4];
            float4 a1 = *(const float4*)&As[cur][kk][ty * 4 + 64];
            float4 b0 = *(const float4*)&Bs[cur][kk][tx * 4];
            float4 b1 = *(const float4*)&Bs[cur][kk][tx * 4 + 64];
            float av[8] = {a0.x, a0.y, a0.z, a0.w, a1.x, a1.y, a1.z, a1.w};
            float bv[8] = {b0.x, b0.y, b0.z, b0.w, b1.x, b1.y, b1.z, b1.w};
            #pragma unroll
            for (int i = 0; i < 8; ++i)
                #pragma unroll
                for (int j = 0; j < 8; ++j)
                    acc[i][j] = fmaf(av[i], bv[j], acc[i][j]);
        }
        if (t + 1 < NT) {
            const int nxt = 1 - cur;
            // store prefetched tile t+1 into the other buffer
            As[nxt][acol + 0][arow] = ra0.x; As[nxt][acol + 1][arow] = ra0.y;
            As[nxt][acol + 2][arow] = ra0.z; As[nxt][acol + 3][arow] = ra0.w;
            As[nxt][acol + 0][arow + 64] = ra1.x; As[nxt][acol + 1][arow + 64] = ra1.y;
            As[nxt][acol + 2][arow + 64] = ra1.z; As[nxt][acol + 3][arow + 64] = ra1.w;
            *(float4*)&Bs[nxt][brow][bcol] = rb0;
            *(float4*)&Bs[nxt][brow + 8][bcol] = rb1;
            __syncthreads();
            if (t + 2 < NT) {
                const int k0 = (t + 2) * BK;
                ra0 = *(const float4*)(Aptr0 + k0);
                ra1 = *(const float4*)(Aptr1 + k0);
                rb0 = *(const float4*)(Bptr0 + (size_t)k0 * N3);
                rb1 = *(const float4*)(Bptr1 + (size_t)k0 * N3);
            }
        }
    }

    // epilogue: bias + store
    float4 bia0 = *(const float4*)(bias + bn + tx * 4);
    float4 bia1 = *(const float4*)(bias + bn + tx * 4 + 64);
    #pragma unroll
    for (int i = 0; i < 8; ++i) {
        int row = bm + ty * 4 + (i < 4 ? i : 60 + i);   // i>=4 -> +64 + (i-4)
        float4 o0, o1;
        o0.x = acc[i][0] + bia0.x; o0.y = acc[i][1] + bia0.y;
        o0.z = acc[i][2] + bia0.z; o0.w = acc[i][3] + bia0.w;
        o1.x = acc[i][4] + bia1.x; o1.y = acc[i][5] + bia1.y;
        o1.z = acc[i][6] + bia1.z; o1.w = acc[i][7] + bia1.w;
        *(float4*)(C + (size_t)row * N3 + bn + tx * 4) = o0;
        *(float4*)(C + (size_t)row * N3 + bn + tx * 4 + 64) = o1;
    }
}

// ---------------------------------------------------------------------------
// SRU scan: sequential over S, parallel over B*H channels.
// c = f*c + (1-f)*u ;  h = o*tanh(c) + (1-o)*x
// ---------------------------------------------------------------------------
__global__ void sru_scan_kernel(const float* __restrict__ gates,
                                const float* __restrict__ xin,
                                const float* __restrict__ c0,
                                float* __restrict__ hout,
                                float* __restrict__ clast)
{
    const int idx = blockIdx.x * blockDim.x + threadIdx.x;   // 0..B*H-1
    if (idx >= BB * HH) return;
    const int b  = idx >> 10;
    const int hh = idx & (HH - 1);

    const float* g = gates + (size_t)b * N3 + hh;
    float c = c0[idx];

    #pragma unroll 8
    for (int s = 0; s < SS; ++s) {
        const size_t go = (size_t)s * BB * N3;
        float u = g[go];
        float f = g[go + HH];
        float o = g[go + 2 * HH];
        f = 1.0f / (1.0f + __expf(-f));
        o = 1.0f / (1.0f + __expf(-o));
        c = f * c + (1.0f - f) * u;
        const size_t xo = (size_t)s * BB * HH + idx;
        float xv = xin[xo];
        hout[xo] = o * tanhf(c) + (1.0f - o) * xv;
    }
    clast[idx] = c;
}

// ---------------------------------------------------------------------------
// kernel_launch
// inputs (metadata order): x, h0, W1, b1, W2, b2
// output: [h2 (S*B*H) | hidden (2*B*H)]
// ---------------------------------------------------------------------------
extern "C" void kernel_launch(void* const* d_in, const int* in_sizes, int n_in,
                              void* d_out, int out_size)
{
    const float* x  = (const float*)d_in[0];
    const float* h0 = (const float*)d_in[1];
    const float* W1 = (const float*)d_in[2];
    const float* b1 = (const float*)d_in[3];
    const float* W2 = (const float*)d_in[4];
    const float* b2 = (const float*)d_in[5];

    float* out    = (float*)d_out;
    float* h2     = out;                              // S*B*H
    float* hidden = out + (size_t)SS * BB * HH;       // 2*B*H

    float* gates = nullptr;
    float* h1    = nullptr;
    cudaGetSymbolAddress((void**)&gates, g_gates);
    cudaGetSymbolAddress((void**)&h1, g_h1);

    dim3 gdim(N3 / BN, MM / BM);   // 24 x 256
    dim3 bdim(256);
    dim3 sgrid((BB * HH) / 128);   // 64 blocks
    dim3 sblk(128);

    // Layer 1
    gemm_bias_kernel<<<gdim, bdim>>>(x, W1, b1, gates);
    sru_scan_kernel<<<sgrid, sblk>>>(gates, x, h0, h1, hidden);
    // Layer 2
    gemm_bias_kernel<<<gdim, bdim>>>(h1, W2, b2, gates);
    sru_scan_kernel<<<sgrid, sblk>>>(gates, h1, h0 + BB * HH, h2, hidden + BB * HH);
}

// round 6
// speedup vs baseline: 1.1625x; 1.1625x over previous
#include <cuda_runtime.h>
#include <cuda_bf16.h>
#include <cstdint>
#include <cstddef>

// Problem constants
#define SSZ  4096
#define BBZ  8
#define HHZ  1024
#define N3Z  3072
#define MMZ  32768          // S*B
#define KKZ  1024

// ---------------- device-global scratch (no allocations allowed) ----------
__device__ float         g_gates[(size_t)MMZ * N3Z];   // 402 MB
__device__ float         g_h1[(size_t)MMZ * HHZ];      // 134 MB
__device__ __nv_bfloat16 g_Ahi[(size_t)MMZ * KKZ];     // 64 MB
__device__ __nv_bfloat16 g_Alo[(size_t)MMZ * KKZ];     // 64 MB
__device__ __nv_bfloat16 g_B1hi[(size_t)N3Z * KKZ];    // 6 MB
__device__ __nv_bfloat16 g_B1lo[(size_t)N3Z * KKZ];
__device__ __nv_bfloat16 g_B2hi[(size_t)N3Z * KKZ];
__device__ __nv_bfloat16 g_B2lo[(size_t)N3Z * KKZ];

// ---------------- PTX helpers (baseline sm_80-class features only) --------
__device__ __forceinline__ uint32_t smem_u32(const void* p) {
    uint32_t a;
    asm("{ .reg .u64 t; cvta.to.shared.u64 t, %1; cvt.u32.u64 %0, t; }"
        : "=r"(a) : "l"(p));
    return a;
}

#define CP16(saddr, gptr) \
    asm volatile("cp.async.cg.shared.global [%0], [%1], 16;" \
                 :: "r"(saddr), "l"(gptr))
#define CP_COMMIT() asm volatile("cp.async.commit_group;" ::: "memory")
#define CP_WAIT(n)  asm volatile("cp.async.wait_group %0;" :: "n"(n) : "memory")

#define LDSM4(r0, r1, r2, r3, addr) \
    asm volatile("ldmatrix.sync.aligned.m8n8.x4.shared.b16 {%0,%1,%2,%3}, [%4];" \
                 : "=r"(r0), "=r"(r1), "=r"(r2), "=r"(r3) : "r"(addr))

#define MMA16816(d, a, b) \
    asm volatile("mma.sync.aligned.m16n8k16.row.col.f32.bf16.bf16.f32 " \
                 "{%0,%1,%2,%3},{%4,%5,%6,%7},{%8,%9},{%0,%1,%2,%3};" \
                 : "+f"((d)[0]), "+f"((d)[1]), "+f"((d)[2]), "+f"((d)[3]) \
                 : "r"((a)[0]), "r"((a)[1]), "r"((a)[2]), "r"((a)[3]), \
                   "r"((b)[0]), "r"((b)[1]))

// ---------------- GEMM geometry -------------------------------------------
// CTA 128x128, K-chunk 64 (bf16), 2-stage cp.async pipeline.
// 8 warps: warp grid 2(m) x 4(n), warp tile 64x32.
#define BM 128
#define BN 128
#define BK 64
#define NT (KKZ / BK)                 // 16 K-chunks
#define VAR_BYTES (128 * 128)         // 128 rows x 128B (BK=64 bf16) = 16 KB
#define OFF_AHI 0
#define OFF_ALO (1 * VAR_BYTES)
#define OFF_BHI (2 * VAR_BYTES)
#define OFF_BLO (3 * VAR_BYTES)
#define STAGE_BYTES (4 * VAR_BYTES)   // 64 KB
#define STAGES_OFF 1024               // [0,1024) = bias + pad
#define SMEM_NEED (STAGES_OFF + 2 * STAGE_BYTES + 1024)

// SW128 swizzle specialized: swz(row*128 + seg*16) = row*128 + ((seg^(row&7))*16)
__device__ __forceinline__ uint32_t swz_rs(uint32_t row, uint32_t seg) {
    return row * 128u + (((seg ^ row) & 7u) << 4);
}

__global__ void __launch_bounds__(256, 1)
gemm_mma(const __nv_bfloat16* __restrict__ Ahi, const __nv_bfloat16* __restrict__ Alo,
         const __nv_bfloat16* __restrict__ Bhi, const __nv_bfloat16* __restrict__ Blo,
         const float* __restrict__ bias, float* __restrict__ C)
{
    extern __shared__ char smraw[];
    const uint32_t sb0 = smem_u32(smraw);
    const uint32_t sb  = (sb0 + 1023u) & ~1023u;        // 1KB align
    char* smp = smraw + (sb - sb0);

    const int tid  = threadIdx.x;
    const int wid  = tid >> 5;
    const int lane = tid & 31;
    const int wm   = wid >> 2;            // 0..1  (m)
    const int wn   = wid & 3;             // 0..3  (n)
    const int bn   = blockIdx.x * BN;
    const int bm   = blockIdx.y * BM;

    // bias tile into smem
    if (tid < 128) ((float*)smp)[tid] = bias[bn + tid];

    // ---- cp.async stage loader: 4 variants x 1024 16B-chunks / 256 thr ----
    const int ldrow = tid >> 3;           // 0..31 base row step handled below
    const int ldseg = tid & 7;            // 0..7 (16B seg within 128B row)
    auto load_stage = [&](int t, int st) {
        const int k0 = t * BK;
        const uint32_t s0 = sb + STAGES_OFF + st * STAGE_BYTES;
        #pragma unroll
        for (int r = 0; r < 4; ++r) {
            const uint32_t row = ldrow + r * 32;
            const uint32_t so = swz_rs(row, ldseg);
            const size_t gA = (size_t)(bm + row) * KKZ + k0 + ldseg * 8;
            const size_t gB = (size_t)(bn + row) * KKZ + k0 + ldseg * 8;
            CP16(s0 + OFF_AHI + so, Ahi + gA);
            CP16(s0 + OFF_ALO + so, Alo + gA);
            CP16(s0 + OFF_BHI + so, Bhi + gB);
            CP16(s0 + OFF_BLO + so, Blo + gB);
        }
    };

    // ---- per-lane ldmatrix row/seg precompute ----
    // A (x4): rows = warp m-tile row + (lane%16); k-half = lane/16
    const uint32_t a_row = (uint32_t)(wm * 64) + (lane & 15);
    const uint32_t a_kh  = (uint32_t)(lane >> 4);          // 0/1
    // B (x4, n16): rows = n-base + (lane%8) + (lane/16)*8 ; k-half = (lane/8)&1
    const uint32_t b_row = (uint32_t)(wn * 32) + (lane & 7) + ((lane >> 4) << 3);
    const uint32_t b_kh  = (uint32_t)((lane >> 3) & 1);

    float acc[4][4][4];
    #pragma unroll
    for (int mi = 0; mi < 4; ++mi)
        #pragma unroll
        for (int ni = 0; ni < 4; ++ni)
            #pragma unroll
            for (int j = 0; j < 4; ++j) acc[mi][ni][j] = 0.0f;

    // ---- pipeline ----
    load_stage(0, 0); CP_COMMIT();

    #pragma unroll 1
    for (int t = 0; t < NT; ++t) {
        if (t + 1 < NT) { load_stage(t + 1, (t + 1) & 1); CP_COMMIT(); }
        if (t + 1 < NT) { CP_WAIT(1); } else { CP_WAIT(0); }
        __syncthreads();

        const uint32_t s0 = sb + STAGES_OFF + (t & 1) * STAGE_BYTES;

        #pragma unroll
        for (int ks = 0; ks < 4; ++ks) {                   // 4 x k16
            uint32_t ah[4][4], al[4][4], bh[2][4], bl[2][4];
            const uint32_t a_seg = (uint32_t)(ks * 2) + a_kh;
            const uint32_t b_seg = (uint32_t)(ks * 2) + b_kh;
            #pragma unroll
            for (int mi = 0; mi < 4; ++mi) {
                const uint32_t so = swz_rs(a_row + mi * 16, a_seg);
                LDSM4(ah[mi][0], ah[mi][1], ah[mi][2], ah[mi][3], s0 + OFF_AHI + so);
                LDSM4(al[mi][0], al[mi][1], al[mi][2], al[mi][3], s0 + OFF_ALO + so);
            }
            #pragma unroll
            for (int nb = 0; nb < 2; ++nb) {
                const uint32_t so = swz_rs(b_row + nb * 16, b_seg);
                LDSM4(bh[nb][0], bh[nb][1], bh[nb][2], bh[nb][3], s0 + OFF_BHI + so);
                LDSM4(bl[nb][0], bl[nb][1], bl[nb][2], bl[nb][3], s0 + OFF_BLO + so);
            }
            // b fragment for n8 tile ni: regs {r[2*(ni&1)], r[2*(ni&1)+1]} of x4 load nb=ni>>1
            #pragma unroll
            for (int mi = 0; mi < 4; ++mi) {
                #pragma unroll
                for (int ni = 0; ni < 4; ++ni) {
                    uint32_t bfr_h[2] = { bh[ni >> 1][2 * (ni & 1)], bh[ni >> 1][2 * (ni & 1) + 1] };
                    uint32_t bfr_l[2] = { bl[ni >> 1][2 * (ni & 1)], bl[ni >> 1][2 * (ni & 1) + 1] };
                    MMA16816(acc[mi][ni], ah[mi], bfr_h);   // hi*hi
                    MMA16816(acc[mi][ni], ah[mi], bfr_l);   // hi*lo
                    MMA16816(acc[mi][ni], al[mi], bfr_h);   // lo*hi
                }
            }
        }
        __syncthreads();   // stage buffer reused by next-next load
    }

    // ---- epilogue: bias + fp32 store ----
    const float* bsm = (const float*)smp;
    #pragma unroll
    for (int mi = 0; mi < 4; ++mi) {
        const int r0 = bm + wm * 64 + mi * 16 + (lane >> 2);
        #pragma unroll
        for (int ni = 0; ni < 4; ++ni) {
            const int cl = wn * 32 + ni * 8 + (lane & 3) * 2;   // local col in [0,128)
            const float b0 = bsm[cl], b1 = bsm[cl + 1];
            float2 v0 = { acc[mi][ni][0] + b0, acc[mi][ni][1] + b1 };
            float2 v1 = { acc[mi][ni][2] + b0, acc[mi][ni][3] + b1 };
            *(float2*)(C + (size_t)r0 * N3Z + bn + cl) = v0;
            *(float2*)(C + (size_t)(r0 + 8) * N3Z + bn + cl) = v1;
        }
    }
}

// ---------------- fp32 -> bf16 hi/lo split --------------------------------
__global__ void split_kernel(const float* __restrict__ in,
                             __nv_bfloat16* __restrict__ hi,
                             __nv_bfloat16* __restrict__ lo)
{
    size_t i = (size_t)blockIdx.x * blockDim.x + threadIdx.x;   // float4 index
    float4 v = ((const float4*)in)[i];
    __nv_bfloat16 h0 = __float2bfloat16(v.x), h1 = __float2bfloat16(v.y);
    __nv_bfloat16 h2 = __float2bfloat16(v.z), h3 = __float2bfloat16(v.w);
    __nv_bfloat162 hp0 = {h0, h1}, hp1 = {h2, h3};
    __nv_bfloat162 lp0 = {__float2bfloat16(v.x - __bfloat162float(h0)),
                          __float2bfloat16(v.y - __bfloat162float(h1))};
    __nv_bfloat162 lp1 = {__float2bfloat16(v.z - __bfloat162float(h2)),
                          __float2bfloat16(v.w - __bfloat162float(h3))};
    ((__nv_bfloat162*)hi)[2*i + 0] = hp0;
    ((__nv_bfloat162*)hi)[2*i + 1] = hp1;
    ((__nv_bfloat162*)lo)[2*i + 0] = lp0;
    ((__nv_bfloat162*)lo)[2*i + 1] = lp1;
}

// ---------------- W[K,N] -> Bt[N,K] transpose + bf16 split -----------------
__global__ void wsplit_kernel(const float* __restrict__ W,
                              __nv_bfloat16* __restrict__ hi,
                              __nv_bfloat16* __restrict__ lo)
{
    __shared__ float t[32][33];
    const int n0 = blockIdx.x * 32, k0 = blockIdx.y * 32;
    const int tx = threadIdx.x, ty = threadIdx.y;   // 32 x 8
    #pragma unroll
    for (int i = 0; i < 4; ++i)
        t[ty + i*8][tx] = W[(size_t)(k0 + ty + i*8) * N3Z + n0 + tx];
    __syncthreads();
    #pragma unroll
    for (int i = 0; i < 4; ++i) {
        float v = t[tx][ty + i*8];
        size_t o = (size_t)(n0 + ty + i*8) * KKZ + k0 + tx;
        __nv_bfloat16 h = __float2bfloat16(v);
        hi[o] = h;
        lo[o] = __float2bfloat16(v - __bfloat162float(h));
    }
}

// ---------------- SRU scan -------------------------------------------------
__global__ void sru_scan_kernel(const float* __restrict__ gates,
                                const float* __restrict__ xin,
                                const float* __restrict__ c0,
                                float* __restrict__ hout,
                                float* __restrict__ clast)
{
    const int idx = blockIdx.x * blockDim.x + threadIdx.x;   // 0..B*H-1
    const int b  = idx >> 10;
    const int hh = idx & (HHZ - 1);

    const float* g = gates + (size_t)b * N3Z + hh;
    float c = c0[idx];

    #pragma unroll 8
    for (int s = 0; s < SSZ; ++s) {
        const size_t go = (size_t)s * BBZ * N3Z;
        float u = g[go];
        float f = g[go + HHZ];
        float o = g[go + 2 * HHZ];
        f = 1.0f / (1.0f + __expf(-f));
        o = 1.0f / (1.0f + __expf(-o));
        c = f * c + (1.0f - f) * u;
        const size_t xo = (size_t)s * BBZ * HHZ + idx;
        float xv = xin[xo];
        hout[xo] = o * tanhf(c) + (1.0f - o) * xv;
    }
    clast[idx] = c;
}

// ---------------- launch ---------------------------------------------------
extern "C" void kernel_launch(void* const* d_in, const int* in_sizes, int n_in,
                              void* d_out, int out_size)
{
    const float* x  = (const float*)d_in[0];
    const float* h0 = (const float*)d_in[1];
    const float* W1 = (const float*)d_in[2];
    const float* b1 = (const float*)d_in[3];
    const float* W2 = (const float*)d_in[4];
    const float* b2 = (const float*)d_in[5];

    float* out    = (float*)d_out;
    float* h2     = out;
    float* hidden = out + (size_t)SSZ * BBZ * HHZ;

    float *gates, *h1;
    __nv_bfloat16 *Ahi, *Alo, *B1hi, *B1lo, *B2hi, *B2lo;
    cudaGetSymbolAddress((void**)&gates, g_gates);
    cudaGetSymbolAddress((void**)&h1,    g_h1);
    cudaGetSymbolAddress((void**)&Ahi,   g_Ahi);
    cudaGetSymbolAddress((void**)&Alo,   g_Alo);
    cudaGetSymbolAddress((void**)&B1hi,  g_B1hi);
    cudaGetSymbolAddress((void**)&B1lo,  g_B1lo);
    cudaGetSymbolAddress((void**)&B2hi,  g_B2hi);
    cudaGetSymbolAddress((void**)&B2lo,  g_B2lo);

    cudaFuncSetAttribute(gemm_mma, cudaFuncAttributeMaxDynamicSharedMemorySize,
                         SMEM_NEED);

    const int nsplit = (MMZ * KKZ / 4) / 256;        // 32768 blocks
    dim3 wgrid(N3Z / 32, KKZ / 32), wblk(32, 8);
    dim3 ggrid(N3Z / BN, MMZ / BM);                  // 24 x 256
    dim3 sgrid((BBZ * HHZ) / 128), sblk(128);

    // weight prep (both layers)
    wsplit_kernel<<<wgrid, wblk>>>(W1, B1hi, B1lo);
    wsplit_kernel<<<wgrid, wblk>>>(W2, B2hi, B2lo);

    // Layer 1
    split_kernel<<<nsplit, 256>>>(x, Ahi, Alo);
    gemm_mma<<<ggrid, 256, SMEM_NEED>>>(Ahi, Alo, B1hi, B1lo, b1, gates);
    sru_scan_kernel<<<sgrid, sblk>>>(gates, x, h0, h1, hidden);

    // Layer 2
    split_kernel<<<nsplit, 256>>>(h1, Ahi, Alo);
    gemm_mma<<<ggrid, 256, SMEM_NEED>>>(Ahi, Alo, B2hi, B2lo, b2, gates);
    sru_scan_kernel<<<sgrid, sblk>>>(gates, h1, h0 + BBZ * HHZ, h2,
                                     hidden + BBZ * HHZ);
}

// round 7
// speedup vs baseline: 1.7281x; 1.4866x over previous
#include <cuda_runtime.h>
#include <cuda_fp16.h>
#include <cstdint>
#include <cstddef>

// Problem constants
#define SSZ  4096
#define BBZ  8
#define HHZ  1024
#define N3Z  3072
#define MMZ  32768          // S*B
#define KKZ  1024

// ---------------- device-global scratch (no allocations allowed) ----------
__device__ float  g_gates[(size_t)MMZ * N3Z];   // 402 MB
__device__ float  g_h1[(size_t)MMZ * HHZ];      // 134 MB
__device__ __half g_Ah[(size_t)MMZ * KKZ];      // 64 MB
__device__ __half g_W1hi[(size_t)N3Z * KKZ];    // 6 MB each
__device__ __half g_W1lo[(size_t)N3Z * KKZ];
__device__ __half g_W2hi[(size_t)N3Z * KKZ];
__device__ __half g_W2lo[(size_t)N3Z * KKZ];

// ---------------- PTX helpers ---------------------------------------------
__device__ __forceinline__ uint32_t smem_u32(const void* p) {
    uint32_t a;
    asm("{ .reg .u64 t; cvta.to.shared.u64 t, %1; cvt.u32.u64 %0, t; }"
        : "=r"(a) : "l"(p));
    return a;
}

#define CP16(saddr, gptr) \
    asm volatile("cp.async.cg.shared.global [%0], [%1], 16;" \
                 :: "r"(saddr), "l"(gptr))
#define CP_COMMIT() asm volatile("cp.async.commit_group;" ::: "memory")
#define CP_WAIT(n)  asm volatile("cp.async.wait_group %0;" :: "n"(n) : "memory")

#define LDSM4(r0, r1, r2, r3, addr) \
    asm volatile("ldmatrix.sync.aligned.m8n8.x4.shared.b16 {%0,%1,%2,%3}, [%4];" \
                 : "=r"(r0), "=r"(r1), "=r"(r2), "=r"(r3) : "r"(addr))

#define MMAF16(d, a, b0, b1) \
    asm volatile("mma.sync.aligned.m16n8k16.row.col.f32.f16.f16.f32 " \
                 "{%0,%1,%2,%3},{%4,%5,%6,%7},{%8,%9},{%0,%1,%2,%3};" \
                 : "+f"((d)[0]), "+f"((d)[1]), "+f"((d)[2]), "+f"((d)[3]) \
                 : "r"((a)[0]), "r"((a)[1]), "r"((a)[2]), "r"((a)[3]), \
                   "r"(b0), "r"(b1))

// ---------------- GEMM geometry -------------------------------------------
// CTA 256x128, K-chunk 64 (fp16 = 128B rows), 3-stage cp.async pipeline,
// one __syncthreads per k-iter. 8 warps: 4(m) x 2(n), warp tile 64x64.
#define BM 256
#define BN 128
#define BK 64
#define NT (KKZ / BK)                 // 16
#define OFF_A  0                      // A: 256 rows x 128B = 32 KB
#define OFF_BH 32768                  // Whi: 128 x 128B = 16 KB
#define OFF_BL 49152                  // Wlo: 16 KB
#define STAGE_BYTES 65536
#define STAGES_OFF 1024               // [0,1024) bias + pad
#define SMEM_NEED (STAGES_OFF + 3 * STAGE_BYTES + 1024)   // ~199 KB

// SW128 swizzle on (row, 16B-seg): conflict-free for cp.async + ldmatrix
__device__ __forceinline__ uint32_t swz_rs(uint32_t row, uint32_t seg) {
    return row * 128u + (((seg ^ row) & 7u) << 4);
}

__global__ void __launch_bounds__(256, 1)
gemm_mma2(const __half* __restrict__ Ah,
          const __half* __restrict__ Whi, const __half* __restrict__ Wlo,
          const float* __restrict__ bias, float* __restrict__ C)
{
    extern __shared__ char smraw[];
    const uint32_t sb0 = smem_u32(smraw);
    const uint32_t sb  = (sb0 + 1023u) & ~1023u;
    char* smp = smraw + (sb - sb0);

    const int tid  = threadIdx.x;
    const int wid  = tid >> 5;
    const int lane = tid & 31;
    const int wm   = wid >> 1;            // 0..3 (m)
    const int wn   = wid & 1;             // 0..1 (n)
    const int bn   = blockIdx.x * BN;
    const int bm   = blockIdx.y * BM;

    if (tid < 128) ((float*)smp)[tid] = bias[bn + tid];

    // loader: 16 cp16 per thread per stage (A:8, Bh:4, Bl:4)
    auto load_stage = [&](int t, int st) {
        const int k0 = t * BK;
        const uint32_t s0 = sb + STAGES_OFF + st * STAGE_BYTES;
        #pragma unroll
        for (int r = 0; r < 8; ++r) {
            const int idx = tid + r * 256;
            const uint32_t row = idx >> 3, seg = idx & 7;
            CP16(s0 + OFF_A + swz_rs(row, seg),
                 Ah + (size_t)(bm + row) * KKZ + k0 + seg * 8);
        }
        #pragma unroll
        for (int r = 0; r < 4; ++r) {
            const int idx = tid + r * 256;
            const uint32_t row = idx >> 3, seg = idx & 7;
            const size_t g = (size_t)(bn + row) * KKZ + k0 + seg * 8;
            const uint32_t so = swz_rs(row, seg);
            CP16(s0 + OFF_BH + so, Whi + g);
            CP16(s0 + OFF_BL + so, Wlo + g);
        }
    };

    // ldmatrix lane mappings (validated in R6)
    const uint32_t a_row = (uint32_t)(wm * 64) + (lane & 15);
    const uint32_t a_kh  = (uint32_t)(lane >> 4);
    const uint32_t b_row = (uint32_t)(wn * 64) + (lane & 7) + ((lane >> 4) << 3);
    const uint32_t b_kh  = (uint32_t)((lane >> 3) & 1);

    float acc[4][8][4];
    #pragma unroll
    for (int mi = 0; mi < 4; ++mi)
        #pragma unroll
        for (int ni = 0; ni < 8; ++ni)
            #pragma unroll
            for (int j = 0; j < 4; ++j) acc[mi][ni][j] = 0.0f;

    load_stage(0, 0); CP_COMMIT();
    load_stage(1, 1); CP_COMMIT();

    #pragma unroll 1
    for (int t = 0; t < NT; ++t) {
        CP_WAIT(1);
        __syncthreads();
        if (t + 2 < NT) { load_stage(t + 2, (t + 2) % 3); CP_COMMIT(); }

        const uint32_t s0 = sb + STAGES_OFF + (t % 3) * STAGE_BYTES;

        #pragma unroll
        for (int ks = 0; ks < 4; ++ks) {
            const uint32_t a_seg = (uint32_t)(ks * 2) + a_kh;
            const uint32_t b_seg = (uint32_t)(ks * 2) + b_kh;
            uint32_t af[4][4], bf[4][4];
            #pragma unroll
            for (int mi = 0; mi < 4; ++mi) {
                const uint32_t so = swz_rs(a_row + mi * 16, a_seg);
                LDSM4(af[mi][0], af[mi][1], af[mi][2], af[mi][3], s0 + OFF_A + so);
            }
            // pass 1: A * W_hi
            #pragma unroll
            for (int nb = 0; nb < 4; ++nb) {
                const uint32_t so = swz_rs(b_row + nb * 16, b_seg);
                LDSM4(bf[nb][0], bf[nb][1], bf[nb][2], bf[nb][3], s0 + OFF_BH + so);
            }
            #pragma unroll
            for (int mi = 0; mi < 4; ++mi)
                #pragma unroll
                for (int ni = 0; ni < 8; ++ni)
                    MMAF16(acc[mi][ni], af[mi],
                           bf[ni >> 1][2 * (ni & 1)], bf[ni >> 1][2 * (ni & 1) + 1]);
            // pass 2: A * W_lo
            #pragma unroll
            for (int nb = 0; nb < 4; ++nb) {
                const uint32_t so = swz_rs(b_row + nb * 16, b_seg);
                LDSM4(bf[nb][0], bf[nb][1], bf[nb][2], bf[nb][3], s0 + OFF_BL + so);
            }
            #pragma unroll
            for (int mi = 0; mi < 4; ++mi)
                #pragma unroll
                for (int ni = 0; ni < 8; ++ni)
                    MMAF16(acc[mi][ni], af[mi],
                           bf[ni >> 1][2 * (ni & 1)], bf[ni >> 1][2 * (ni & 1) + 1]);
        }
    }

    // epilogue: bias + fp32 store
    const float* bsm = (const float*)smp;
    #pragma unroll
    for (int mi = 0; mi < 4; ++mi) {
        const int r0 = bm + wm * 64 + mi * 16 + (lane >> 2);
        #pragma unroll
        for (int ni = 0; ni < 8; ++ni) {
            const int cl = wn * 64 + ni * 8 + (lane & 3) * 2;
            const float b0 = bsm[cl], b1 = bsm[cl + 1];
            float2 v0 = { acc[mi][ni][0] + b0, acc[mi][ni][1] + b1 };
            float2 v1 = { acc[mi][ni][2] + b0, acc[mi][ni][3] + b1 };
            *(float2*)(C + (size_t)r0 * N3Z + bn + cl) = v0;
            *(float2*)(C + (size_t)(r0 + 8) * N3Z + bn + cl) = v1;
        }
    }
}

// ---------------- fp32 -> fp16 convert (A side) ----------------------------
__global__ void tofp16_kernel(const float* __restrict__ in,
                              __half* __restrict__ out)
{
    size_t i = (size_t)blockIdx.x * blockDim.x + threadIdx.x;   // float4 idx
    float4 v = ((const float4*)in)[i];
    __half2 p0 = __floats2half2_rn(v.x, v.y);
    __half2 p1 = __floats2half2_rn(v.z, v.w);
    ((__half2*)out)[2 * i + 0] = p0;
    ((__half2*)out)[2 * i + 1] = p1;
}

// ---------------- W[K,N] -> Wt[N,K] transpose + fp16 hi/lo split -----------
__global__ void wsplit_kernel(const float* __restrict__ W,
                              __half* __restrict__ hi,
                              __half* __restrict__ lo)
{
    __shared__ float t[32][33];
    const int n0 = blockIdx.x * 32, k0 = blockIdx.y * 32;
    const int tx = threadIdx.x, ty = threadIdx.y;   // 32 x 8
    #pragma unroll
    for (int i = 0; i < 4; ++i)
        t[ty + i*8][tx] = W[(size_t)(k0 + ty + i*8) * N3Z + n0 + tx];
    __syncthreads();
    #pragma unroll
    for (int i = 0; i < 4; ++i) {
        float v = t[tx][ty + i*8];
        size_t o = (size_t)(n0 + ty + i*8) * KKZ + k0 + tx;
        __half h = __float2half_rn(v);
        hi[o] = h;
        lo[o] = __float2half_rn(v - __half2float(h));
    }
}

// ---------------- SRU scan -------------------------------------------------
__global__ void sru_scan_kernel(const float* __restrict__ gates,
                                const float* __restrict__ xin,
                                const float* __restrict__ c0,
                                float* __restrict__ hout,
                                float* __restrict__ clast)
{
    const int idx = blockIdx.x * blockDim.x + threadIdx.x;   // 0..B*H-1
    const int b  = idx >> 10;
    const int hh = idx & (HHZ - 1);

    const float* g = gates + (size_t)b * N3Z + hh;
    float c = c0[idx];

    #pragma unroll 8
    for (int s = 0; s < SSZ; ++s) {
        const size_t go = (size_t)s * BBZ * N3Z;
        float u = g[go];
        float f = g[go + HHZ];
        float o = g[go + 2 * HHZ];
        f = 1.0f / (1.0f + __expf(-f));
        o = 1.0f / (1.0f + __expf(-o));
        c = f * c + (1.0f - f) * u;
        const size_t xo = (size_t)s * BBZ * HHZ + idx;
        float xv = xin[xo];
        hout[xo] = o * tanhf(c) + (1.0f - o) * xv;
    }
    clast[idx] = c;
}

// ---------------- launch ---------------------------------------------------
extern "C" void kernel_launch(void* const* d_in, const int* in_sizes, int n_in,
                              void* d_out, int out_size)
{
    const float* x  = (const float*)d_in[0];
    const float* h0 = (const float*)d_in[1];
    const float* W1 = (const float*)d_in[2];
    const float* b1 = (const float*)d_in[3];
    const float* W2 = (const float*)d_in[4];
    const float* b2 = (const float*)d_in[5];

    float* out    = (float*)d_out;
    float* h2     = out;
    float* hidden = out + (size_t)SSZ * BBZ * HHZ;

    float *gates, *h1;
    __half *Ah, *W1hi, *W1lo, *W2hi, *W2lo;
    cudaGetSymbolAddress((void**)&gates, g_gates);
    cudaGetSymbolAddress((void**)&h1,    g_h1);
    cudaGetSymbolAddress((void**)&Ah,    g_Ah);
    cudaGetSymbolAddress((void**)&W1hi,  g_W1hi);
    cudaGetSymbolAddress((void**)&W1lo,  g_W1lo);
    cudaGetSymbolAddress((void**)&W2hi,  g_W2hi);
    cudaGetSymbolAddress((void**)&W2lo,  g_W2lo);

    cudaFuncSetAttribute(gemm_mma2, cudaFuncAttributeMaxDynamicSharedMemorySize,
                         SMEM_NEED);

    const int ncv = (MMZ * KKZ / 4) / 256;           // 32768 blocks
    dim3 wgrid(N3Z / 32, KKZ / 32), wblk(32, 8);
    dim3 ggrid(N3Z / BN, MMZ / BM);                  // 24 x 128
    dim3 sgrid((BBZ * HHZ) / 128), sblk(128);

    // weight prep
    wsplit_kernel<<<wgrid, wblk>>>(W1, W1hi, W1lo);
    wsplit_kernel<<<wgrid, wblk>>>(W2, W2hi, W2lo);

    // Layer 1
    tofp16_kernel<<<ncv, 256>>>(x, Ah);
    gemm_mma2<<<ggrid, 256, SMEM_NEED>>>(Ah, W1hi, W1lo, b1, gates);
    sru_scan_kernel<<<sgrid, sblk>>>(gates, x, h0, h1, hidden);

    // Layer 2
    tofp16_kernel<<<ncv, 256>>>(h1, Ah);
    gemm_mma2<<<ggrid, 256, SMEM_NEED>>>(Ah, W2hi, W2lo, b2, gates);
    sru_scan_kernel<<<sgrid, sblk>>>(gates, h1, h0 + BBZ * HHZ, h2,
                                     hidden + BBZ * HHZ);
}

// round 8
// speedup vs baseline: 4.8711x; 2.8187x over previous
#include <cuda_runtime.h>
#include <cuda_fp16.h>
#include <cstdint>
#include <cstddef>

// Problem constants
#define SSZ  4096
#define BBZ  8
#define HHZ  1024
#define N3Z  3072
#define MMZ  32768          // S*B
#define KKZ  1024
#define CHN  (BBZ * HHZ)    // 8192 channels
#define CS   64             // scan chunk length
#define NC   (SSZ / CS)     // 64 chunks

// ---------------- device-global scratch (no allocations allowed) ----------
__device__ float  g_gates[(size_t)MMZ * N3Z];   // 402 MB
__device__ float  g_h1[(size_t)MMZ * HHZ];      // 134 MB
__device__ __half g_Ah[(size_t)MMZ * KKZ];      // 64 MB
__device__ __half g_W1hi[(size_t)N3Z * KKZ];    // 6 MB each
__device__ __half g_W1lo[(size_t)N3Z * KKZ];
__device__ __half g_W2hi[(size_t)N3Z * KKZ];
__device__ __half g_W2lo[(size_t)N3Z * KKZ];
__device__ float  g_scanP[(size_t)NC * CHN];    // chunk f-products
__device__ float  g_scanE[(size_t)NC * CHN];    // chunk partial endpoints
__device__ float  g_scanC[(size_t)NC * CHN];    // chunk carry-ins

// ---------------- PTX helpers ---------------------------------------------
__device__ __forceinline__ uint32_t smem_u32(const void* p) {
    uint32_t a;
    asm("{ .reg .u64 t; cvta.to.shared.u64 t, %1; cvt.u32.u64 %0, t; }"
        : "=r"(a) : "l"(p));
    return a;
}

#define CP16(saddr, gptr) \
    asm volatile("cp.async.cg.shared.global [%0], [%1], 16;" \
                 :: "r"(saddr), "l"(gptr))
#define CP_COMMIT() asm volatile("cp.async.commit_group;" ::: "memory")
#define CP_WAIT(n)  asm volatile("cp.async.wait_group %0;" :: "n"(n) : "memory")

#define LDSM4(r0, r1, r2, r3, addr) \
    asm volatile("ldmatrix.sync.aligned.m8n8.x4.shared.b16 {%0,%1,%2,%3}, [%4];" \
                 : "=r"(r0), "=r"(r1), "=r"(r2), "=r"(r3) : "r"(addr))

#define MMAF16(d, a, b0, b1) \
    asm volatile("mma.sync.aligned.m16n8k16.row.col.f32.f16.f16.f32 " \
                 "{%0,%1,%2,%3},{%4,%5,%6,%7},{%8,%9},{%0,%1,%2,%3};" \
                 : "+f"((d)[0]), "+f"((d)[1]), "+f"((d)[2]), "+f"((d)[3]) \
                 : "r"((a)[0]), "r"((a)[1]), "r"((a)[2]), "r"((a)[3]), \
                   "r"(b0), "r"(b1))

// ---------------- GEMM (unchanged from R7: 256x128, 3-stage, fp16 2-pass) --
#define BM 256
#define BN 128
#define BK 64
#define NT (KKZ / BK)
#define OFF_A  0
#define OFF_BH 32768
#define OFF_BL 49152
#define STAGE_BYTES 65536
#define STAGES_OFF 1024
#define SMEM_NEED (STAGES_OFF + 3 * STAGE_BYTES + 1024)

__device__ __forceinline__ uint32_t swz_rs(uint32_t row, uint32_t seg) {
    return row * 128u + (((seg ^ row) & 7u) << 4);
}

__global__ void __launch_bounds__(256, 1)
gemm_mma2(const __half* __restrict__ Ah,
          const __half* __restrict__ Whi, const __half* __restrict__ Wlo,
          const float* __restrict__ bias, float* __restrict__ C)
{
    extern __shared__ char smraw[];
    const uint32_t sb0 = smem_u32(smraw);
    const uint32_t sb  = (sb0 + 1023u) & ~1023u;
    char* smp = smraw + (sb - sb0);

    const int tid  = threadIdx.x;
    const int wid  = tid >> 5;
    const int lane = tid & 31;
    const int wm   = wid >> 1;
    const int wn   = wid & 1;
    const int bn   = blockIdx.x * BN;
    const int bm   = blockIdx.y * BM;

    if (tid < 128) ((float*)smp)[tid] = bias[bn + tid];

    auto load_stage = [&](int t, int st) {
        const int k0 = t * BK;
        const uint32_t s0 = sb + STAGES_OFF + st * STAGE_BYTES;
        #pragma unroll
        for (int r = 0; r < 8; ++r) {
            const int idx = tid + r * 256;
            const uint32_t row = idx >> 3, seg = idx & 7;
            CP16(s0 + OFF_A + swz_rs(row, seg),
                 Ah + (size_t)(bm + row) * KKZ + k0 + seg * 8);
        }
        #pragma unroll
        for (int r = 0; r < 4; ++r) {
            const int idx = tid + r * 256;
            const uint32_t row = idx >> 3, seg = idx & 7;
            const size_t g = (size_t)(bn + row) * KKZ + k0 + seg * 8;
            const uint32_t so = swz_rs(row, seg);
            CP16(s0 + OFF_BH + so, Whi + g);
            CP16(s0 + OFF_BL + so, Wlo + g);
        }
    };

    const uint32_t a_row = (uint32_t)(wm * 64) + (lane & 15);
    const uint32_t a_kh  = (uint32_t)(lane >> 4);
    const uint32_t b_row = (uint32_t)(wn * 64) + (lane & 7) + ((lane >> 4) << 3);
    const uint32_t b_kh  = (uint32_t)((lane >> 3) & 1);

    float acc[4][8][4];
    #pragma unroll
    for (int mi = 0; mi < 4; ++mi)
        #pragma unroll
        for (int ni = 0; ni < 8; ++ni)
            #pragma unroll
            for (int j = 0; j < 4; ++j) acc[mi][ni][j] = 0.0f;

    load_stage(0, 0); CP_COMMIT();
    load_stage(1, 1); CP_COMMIT();

    #pragma unroll 1
    for (int t = 0; t < NT; ++t) {
        CP_WAIT(1);
        __syncthreads();
        if (t + 2 < NT) { load_stage(t + 2, (t + 2) % 3); CP_COMMIT(); }

        const uint32_t s0 = sb + STAGES_OFF + (t % 3) * STAGE_BYTES;

        #pragma unroll
        for (int ks = 0; ks < 4; ++ks) {
            const uint32_t a_seg = (uint32_t)(ks * 2) + a_kh;
            const uint32_t b_seg = (uint32_t)(ks * 2) + b_kh;
            uint32_t af[4][4], bf[4][4];
            #pragma unroll
            for (int mi = 0; mi < 4; ++mi) {
                const uint32_t so = swz_rs(a_row + mi * 16, a_seg);
                LDSM4(af[mi][0], af[mi][1], af[mi][2], af[mi][3], s0 + OFF_A + so);
            }
            #pragma unroll
            for (int nb = 0; nb < 4; ++nb) {
                const uint32_t so = swz_rs(b_row + nb * 16, b_seg);
                LDSM4(bf[nb][0], bf[nb][1], bf[nb][2], bf[nb][3], s0 + OFF_BH + so);
            }
            #pragma unroll
            for (int mi = 0; mi < 4; ++mi)
                #pragma unroll
                for (int ni = 0; ni < 8; ++ni)
                    MMAF16(acc[mi][ni], af[mi],
                           bf[ni >> 1][2 * (ni & 1)], bf[ni >> 1][2 * (ni & 1) + 1]);
            #pragma unroll
            for (int nb = 0; nb < 4; ++nb) {
                const uint32_t so = swz_rs(b_row + nb * 16, b_seg);
                LDSM4(bf[nb][0], bf[nb][1], bf[nb][2], bf[nb][3], s0 + OFF_BL + so);
            }
            #pragma unroll
            for (int mi = 0; mi < 4; ++mi)
                #pragma unroll
                for (int ni = 0; ni < 8; ++ni)
                    MMAF16(acc[mi][ni], af[mi],
                           bf[ni >> 1][2 * (ni & 1)], bf[ni >> 1][2 * (ni & 1) + 1]);
        }
    }

    const float* bsm = (const float*)smp;
    #pragma unroll
    for (int mi = 0; mi < 4; ++mi) {
        const int r0 = bm + wm * 64 + mi * 16 + (lane >> 2);
        #pragma unroll
        for (int ni = 0; ni < 8; ++ni) {
            const int cl = wn * 64 + ni * 8 + (lane & 3) * 2;
            const float b0 = bsm[cl], b1 = bsm[cl + 1];
            float2 v0 = { acc[mi][ni][0] + b0, acc[mi][ni][1] + b1 };
            float2 v1 = { acc[mi][ni][2] + b0, acc[mi][ni][3] + b1 };
            *(float2*)(C + (size_t)r0 * N3Z + bn + cl) = v0;
            *(float2*)(C + (size_t)(r0 + 8) * N3Z + bn + cl) = v1;
        }
    }
}

// ---------------- fp32 -> fp16 convert -------------------------------------
__global__ void tofp16_kernel(const float* __restrict__ in,
                              __half* __restrict__ out)
{
    size_t i = (size_t)blockIdx.x * blockDim.x + threadIdx.x;
    float4 v = ((const float4*)in)[i];
    ((__half2*)out)[2 * i + 0] = __floats2half2_rn(v.x, v.y);
    ((__half2*)out)[2 * i + 1] = __floats2half2_rn(v.z, v.w);
}

// ---------------- W[K,N] -> Wt[N,K] transpose + fp16 hi/lo split -----------
__global__ void wsplit_kernel(const float* __restrict__ W,
                              __half* __restrict__ hi,
                              __half* __restrict__ lo)
{
    __shared__ float t[32][33];
    const int n0 = blockIdx.x * 32, k0 = blockIdx.y * 32;
    const int tx = threadIdx.x, ty = threadIdx.y;
    #pragma unroll
    for (int i = 0; i < 4; ++i)
        t[ty + i*8][tx] = W[(size_t)(k0 + ty + i*8) * N3Z + n0 + tx];
    __syncthreads();
    #pragma unroll
    for (int i = 0; i < 4; ++i) {
        float v = t[tx][ty + i*8];
        size_t o = (size_t)(n0 + ty + i*8) * KKZ + k0 + tx;
        __half h = __float2half_rn(v);
        hi[o] = h;
        lo[o] = __float2half_rn(v - __half2float(h));
    }
}

// ---------------- chunked SRU scan -----------------------------------------
__device__ __forceinline__ float sigm(float v) {
    return 1.0f / (1.0f + __expf(-v));
}

// Pass 1: per (channel, chunk) partial scan from 0; emit prod(f), end value.
__global__ void scan_pass1(const float* __restrict__ gates,
                           float* __restrict__ P, float* __restrict__ E)
{
    const int idx = blockIdx.x * blockDim.x + threadIdx.x;   // 0..NC*CHN-1
    const int ch = idx & (CHN - 1);
    const int j  = idx >> 13;
    const int b  = ch >> 10;
    const int hh = ch & (HHZ - 1);

    const float* g = gates + (size_t)b * N3Z + hh;
    float c = 0.0f, p = 1.0f;
    const int s0 = j * CS;
    #pragma unroll 4
    for (int s = s0; s < s0 + CS; ++s) {
        const size_t go = (size_t)s * BBZ * N3Z;
        float u = g[go];
        float f = sigm(g[go + HHZ]);
        c = f * c + (1.0f - f) * u;
        p *= f;
    }
    P[(size_t)j * CHN + ch] = p;
    E[(size_t)j * CHN + ch] = c;
}

// Pass 2: sequential carry propagation across chunks (exact reconstruction).
__global__ void scan_pass2(const float* __restrict__ P, const float* __restrict__ E,
                           const float* __restrict__ c0,
                           float* __restrict__ carry, float* __restrict__ clast)
{
    const int ch = blockIdx.x * blockDim.x + threadIdx.x;    // 0..CHN-1
    float c = c0[ch];
    #pragma unroll 8
    for (int j = 0; j < NC; ++j) {
        carry[(size_t)j * CHN + ch] = c;
        c = E[(size_t)j * CHN + ch] + P[(size_t)j * CHN + ch] * c;
    }
    clast[ch] = c;
}

// Pass 3: redo in-chunk scan with true carry; compute h (+ optional fp16 copy).
__global__ void scan_pass3(const float* __restrict__ gates,
                           const float* __restrict__ xin,
                           const float* __restrict__ carry,
                           float* __restrict__ hout,
                           __half* __restrict__ hout_h)
{
    const int idx = blockIdx.x * blockDim.x + threadIdx.x;
    const int ch = idx & (CHN - 1);
    const int j  = idx >> 13;
    const int b  = ch >> 10;
    const int hh = ch & (HHZ - 1);

    const float* g = gates + (size_t)b * N3Z + hh;
    float c = carry[(size_t)j * CHN + ch];
    const int s0 = j * CS;
    #pragma unroll 4
    for (int s = s0; s < s0 + CS; ++s) {
        const size_t go = (size_t)s * BBZ * N3Z;
        float u = g[go];
        float f = sigm(g[go + HHZ]);
        float o = sigm(g[go + 2 * HHZ]);
        c = f * c + (1.0f - f) * u;
        const size_t xo = (size_t)s * CHN + ch;
        float h = o * tanhf(c) + (1.0f - o) * xin[xo];
        hout[xo] = h;
        if (hout_h) hout_h[xo] = __float2half_rn(h);
    }
}

// ---------------- launch ---------------------------------------------------
extern "C" void kernel_launch(void* const* d_in, const int* in_sizes, int n_in,
                              void* d_out, int out_size)
{
    const float* x  = (const float*)d_in[0];
    const float* h0 = (const float*)d_in[1];
    const float* W1 = (const float*)d_in[2];
    const float* b1 = (const float*)d_in[3];
    const float* W2 = (const float*)d_in[4];
    const float* b2 = (const float*)d_in[5];

    float* out    = (float*)d_out;
    float* h2     = out;
    float* hidden = out + (size_t)SSZ * CHN;

    float *gates, *h1, *sP, *sE, *sC;
    __half *Ah, *W1hi, *W1lo, *W2hi, *W2lo;
    cudaGetSymbolAddress((void**)&gates, g_gates);
    cudaGetSymbolAddress((void**)&h1,    g_h1);
    cudaGetSymbolAddress((void**)&Ah,    g_Ah);
    cudaGetSymbolAddress((void**)&W1hi,  g_W1hi);
    cudaGetSymbolAddress((void**)&W1lo,  g_W1lo);
    cudaGetSymbolAddress((void**)&W2hi,  g_W2hi);
    cudaGetSymbolAddress((void**)&W2lo,  g_W2lo);
    cudaGetSymbolAddress((void**)&sP,    g_scanP);
    cudaGetSymbolAddress((void**)&sE,    g_scanE);
    cudaGetSymbolAddress((void**)&sC,    g_scanC);

    cudaFuncSetAttribute(gemm_mma2, cudaFuncAttributeMaxDynamicSharedMemorySize,
                         SMEM_NEED);

    const int ncv = (MMZ * KKZ / 4) / 256;
    dim3 wgrid(N3Z / 32, KKZ / 32), wblk(32, 8);
    dim3 ggrid(N3Z / BN, MMZ / BM);
    const int pgrid = (NC * CHN) / 256;      // 2048 blocks
    const int cgrid = CHN / 256;             // 32 blocks

    // weight prep
    wsplit_kernel<<<wgrid, wblk>>>(W1, W1hi, W1lo);
    wsplit_kernel<<<wgrid, wblk>>>(W2, W2hi, W2lo);

    // Layer 1
    tofp16_kernel<<<ncv, 256>>>(x, Ah);
    gemm_mma2<<<ggrid, 256, SMEM_NEED>>>(Ah, W1hi, W1lo, b1, gates);
    scan_pass1<<<pgrid, 256>>>(gates, sP, sE);
    scan_pass2<<<cgrid, 256>>>(sP, sE, h0, sC, hidden);
    scan_pass3<<<pgrid, 256>>>(gates, x, sC, h1, Ah);   // h1 fp32 + fp16

    // Layer 2
    gemm_mma2<<<ggrid, 256, SMEM_NEED>>>(Ah, W2hi, W2lo, b2, gates);
    scan_pass1<<<pgrid, 256>>>(gates, sP, sE);
    scan_pass2<<<cgrid, 256>>>(sP, sE, h0 + CHN, sC, hidden + CHN);
    scan_pass3<<<pgrid, 256>>>(gates, h1, sC, h2, (__half*)nullptr);
}

// round 10
// speedup vs baseline: 6.7768x; 1.3912x over previous
#include <cuda_runtime.h>
#include <cuda_fp16.h>
#include <cstdint>
#include <cstddef>

// Problem constants
#define SSZ  4096
#define BBZ  8
#define HHZ  1024
#define N3Z  3072
#define MMZ  32768          // S*B
#define KKZ  1024
#define CHN  (BBZ * HHZ)    // 8192 channels
#define CS   64             // scan chunk length
#define NC   (SSZ / CS)     // 64 chunks

// ---------------- device-global scratch (no allocations allowed) ----------
__device__ float  g_gates[(size_t)MMZ * N3Z];   // 402 MB
__device__ __half g_Ah[(size_t)MMZ * KKZ];      // 64 MB (x fp16, then h1 fp16)
__device__ __half g_W1h[(size_t)N3Z * KKZ];     // 6 MB
__device__ __half g_W2h[(size_t)N3Z * KKZ];     // 6 MB
__device__ float  g_scanP[(size_t)NC * CHN];
__device__ float  g_scanE[(size_t)NC * CHN];
__device__ float  g_scanC[(size_t)NC * CHN];

// ---------------- PTX helpers ---------------------------------------------
__device__ __forceinline__ uint32_t smem_u32(const void* p) {
    uint32_t a;
    asm("{ .reg .u64 t; cvta.to.shared.u64 t, %1; cvt.u32.u64 %0, t; }"
        : "=r"(a) : "l"(p));
    return a;
}

#define CP16(saddr, gptr) \
    asm volatile("cp.async.cg.shared.global [%0], [%1], 16;" \
                 :: "r"(saddr), "l"(gptr))
#define CP_COMMIT() asm volatile("cp.async.commit_group;" ::: "memory")
#define CP_WAIT(n)  asm volatile("cp.async.wait_group %0;" :: "n"(n) : "memory")

#define LDSM4(r0, r1, r2, r3, addr) \
    asm volatile("ldmatrix.sync.aligned.m8n8.x4.shared.b16 {%0,%1,%2,%3}, [%4];" \
                 : "=r"(r0), "=r"(r1), "=r"(r2), "=r"(r3) : "r"(addr))

#define MMAF16(d, a, b0, b1) \
    asm volatile("mma.sync.aligned.m16n8k16.row.col.f32.f16.f16.f32 " \
                 "{%0,%1,%2,%3},{%4,%5,%6,%7},{%8,%9},{%0,%1,%2,%3};" \
                 : "+f"((d)[0]), "+f"((d)[1]), "+f"((d)[2]), "+f"((d)[3]) \
                 : "r"((a)[0]), "r"((a)[1]), "r"((a)[2]), "r"((a)[3]), \
                   "r"(b0), "r"(b1))

// ---------------- GEMM: 256x128 CTA, fp16 1-pass, 4-stage cp.async --------
#define BM 256
#define BN 128
#define BK 64
#define NT (KKZ / BK)                 // 16
#define OFF_A  0                      // A: 256 x 128B = 32 KB
#define OFF_B  32768                  // W: 128 x 128B = 16 KB
#define STAGE_BYTES 49152             // 48 KB
#define NSTG 4
#define STAGES_OFF 1024
#define SMEM_NEED (STAGES_OFF + NSTG * STAGE_BYTES + 1024)   // ~198 KB

__device__ __forceinline__ uint32_t swz_rs(uint32_t row, uint32_t seg) {
    return row * 128u + (((seg ^ row) & 7u) << 4);
}

__global__ void __launch_bounds__(256, 1)
gemm_mma2(const __half* __restrict__ Ah, const __half* __restrict__ Wh,
          const float* __restrict__ bias, float* __restrict__ C)
{
    extern __shared__ char smraw[];
    const uint32_t sb0 = smem_u32(smraw);
    const uint32_t sb  = (sb0 + 1023u) & ~1023u;
    char* smp = smraw + (sb - sb0);

    const int tid  = threadIdx.x;
    const int wid  = tid >> 5;
    const int lane = tid & 31;
    const int wm   = wid >> 1;            // 0..3 (m)
    const int wn   = wid & 1;             // 0..1 (n)
    const int bn   = blockIdx.x * BN;
    const int bm   = blockIdx.y * BM;

    if (tid < 128) ((float*)smp)[tid] = bias[bn + tid];

    // loader: 12 cp16 per thread per stage (A:8, B:4)
    auto load_stage = [&](int t, int st) {
        const int k0 = t * BK;
        const uint32_t s0 = sb + STAGES_OFF + st * STAGE_BYTES;
        #pragma unroll
        for (int r = 0; r < 8; ++r) {
            const int idx = tid + r * 256;
            const uint32_t row = idx >> 3, seg = idx & 7;
            CP16(s0 + OFF_A + swz_rs(row, seg),
                 Ah + (size_t)(bm + row) * KKZ + k0 + seg * 8);
        }
        #pragma unroll
        for (int r = 0; r < 4; ++r) {
            const int idx = tid + r * 256;
            const uint32_t row = idx >> 3, seg = idx & 7;
            CP16(s0 + OFF_B + swz_rs(row, seg),
                 Wh + (size_t)(bn + row) * KKZ + k0 + seg * 8);
        }
    };

    const uint32_t a_row = (uint32_t)(wm * 64) + (lane & 15);
    const uint32_t a_kh  = (uint32_t)(lane >> 4);
    const uint32_t b_row = (uint32_t)(wn * 64) + (lane & 7) + ((lane >> 4) << 3);
    const uint32_t b_kh  = (uint32_t)((lane >> 3) & 1);

    float acc[4][8][4];
    #pragma unroll
    for (int mi = 0; mi < 4; ++mi)
        #pragma unroll
        for (int ni = 0; ni < 8; ++ni)
            #pragma unroll
            for (int j = 0; j < 4; ++j) acc[mi][ni][j] = 0.0f;

    load_stage(0, 0); CP_COMMIT();
    load_stage(1, 1); CP_COMMIT();
    load_stage(2, 2); CP_COMMIT();

    #pragma unroll 1
    for (int t = 0; t < NT; ++t) {
        CP_WAIT(2);                       // stage t complete (uniform groups)
        __syncthreads();
        if (t + 3 < NT) load_stage(t + 3, (t + 3) & (NSTG - 1));
        CP_COMMIT();                      // unconditional: keeps group count exact

        const uint32_t s0 = sb + STAGES_OFF + (t & (NSTG - 1)) * STAGE_BYTES;

        #pragma unroll
        for (int ks = 0; ks < 4; ++ks) {
            const uint32_t a_seg = (uint32_t)(ks * 2) + a_kh;
            const uint32_t b_seg = (uint32_t)(ks * 2) + b_kh;
            uint32_t af[4][4], bf[4][4];
            #pragma unroll
            for (int mi = 0; mi < 4; ++mi) {
                const uint32_t so = swz_rs(a_row + mi * 16, a_seg);
                LDSM4(af[mi][0], af[mi][1], af[mi][2], af[mi][3], s0 + OFF_A + so);
            }
            #pragma unroll
            for (int nb = 0; nb < 4; ++nb) {
                const uint32_t so = swz_rs(b_row + nb * 16, b_seg);
                LDSM4(bf[nb][0], bf[nb][1], bf[nb][2], bf[nb][3], s0 + OFF_B + so);
            }
            #pragma unroll
            for (int mi = 0; mi < 4; ++mi)
                #pragma unroll
                for (int ni = 0; ni < 8; ++ni)
                    MMAF16(acc[mi][ni], af[mi],
                           bf[ni >> 1][2 * (ni & 1)], bf[ni >> 1][2 * (ni & 1) + 1]);
        }
    }

    const float* bsm = (const float*)smp;
    #pragma unroll
    for (int mi = 0; mi < 4; ++mi) {
        const int r0 = bm + wm * 64 + mi * 16 + (lane >> 2);
        #pragma unroll
        for (int ni = 0; ni < 8; ++ni) {
            const int cl = wn * 64 + ni * 8 + (lane & 3) * 2;
            const float b0 = bsm[cl], b1 = bsm[cl + 1];
            float2 v0 = { acc[mi][ni][0] + b0, acc[mi][ni][1] + b1 };
            float2 v1 = { acc[mi][ni][2] + b0, acc[mi][ni][3] + b1 };
            *(float2*)(C + (size_t)r0 * N3Z + bn + cl) = v0;
            *(float2*)(C + (size_t)(r0 + 8) * N3Z + bn + cl) = v1;
        }
    }
}

// ---------------- fp32 -> fp16 convert -------------------------------------
__global__ void tofp16_kernel(const float* __restrict__ in,
                              __half* __restrict__ out)
{
    size_t i = (size_t)blockIdx.x * blockDim.x + threadIdx.x;
    float4 v = ((const float4*)in)[i];
    ((__half2*)out)[2 * i + 0] = __floats2half2_rn(v.x, v.y);
    ((__half2*)out)[2 * i + 1] = __floats2half2_rn(v.z, v.w);
}

// ---------------- W[K,N] -> Wt[N,K] transpose + fp16 convert ---------------
__global__ void wtrans_kernel(const float* __restrict__ W,
                              __half* __restrict__ hi)
{
    __shared__ float t[32][33];
    const int n0 = blockIdx.x * 32, k0 = blockIdx.y * 32;
    const int tx = threadIdx.x, ty = threadIdx.y;   // 32 x 8
    #pragma unroll
    for (int i = 0; i < 4; ++i)
        t[ty + i*8][tx] = W[(size_t)(k0 + ty + i*8) * N3Z + n0 + tx];
    __syncthreads();
    #pragma unroll
    for (int i = 0; i < 4; ++i) {
        float v = t[tx][ty + i*8];
        hi[(size_t)(n0 + ty + i*8) * KKZ + k0 + tx] = __float2half_rn(v);
    }
}

// ---------------- chunked SRU scan -----------------------------------------
__device__ __forceinline__ float sigm(float v) {
    return 1.0f / (1.0f + __expf(-v));
}

// Pass 1: per (channel, chunk) partial scan from 0; emit prod(f), end value.
__global__ void scan_pass1(const float* __restrict__ gates,
                           float* __restrict__ P, float* __restrict__ E)
{
    const int idx = blockIdx.x * blockDim.x + threadIdx.x;
    const int ch = idx & (CHN - 1);
    const int j  = idx >> 13;
    const int b  = ch >> 10;
    const int hh = ch & (HHZ - 1);

    const float* g = gates + (size_t)b * N3Z + hh;
    float c = 0.0f, p = 1.0f;
    const int s0 = j * CS;
    #pragma unroll 4
    for (int s = s0; s < s0 + CS; ++s) {
        const size_t go = (size_t)s * BBZ * N3Z;
        float u = g[go];
        float f = sigm(g[go + HHZ]);
        c = f * c + (1.0f - f) * u;
        p *= f;
    }
    P[(size_t)j * CHN + ch] = p;
    E[(size_t)j * CHN + ch] = c;
}

// Pass 2: sequential carry propagation across chunks (exact).
__global__ void scan_pass2(const float* __restrict__ P, const float* __restrict__ E,
                           const float* __restrict__ c0,
                           float* __restrict__ carry, float* __restrict__ clast)
{
    const int ch = blockIdx.x * blockDim.x + threadIdx.x;
    float c = c0[ch];
    #pragma unroll 8
    for (int j = 0; j < NC; ++j) {
        carry[(size_t)j * CHN + ch] = c;
        c = E[(size_t)j * CHN + ch] + P[(size_t)j * CHN + ch] * c;
    }
    clast[ch] = c;
}

// Pass 3a (layer 1): xin fp32, h out as fp16 only (becomes next layer's A).
__global__ void scan_pass3_a(const float* __restrict__ gates,
                             const float* __restrict__ xin,
                             const float* __restrict__ carry,
                             __half* __restrict__ hout_h)
{
    const int idx = blockIdx.x * blockDim.x + threadIdx.x;
    const int ch = idx & (CHN - 1);
    const int j  = idx >> 13;
    const int b  = ch >> 10;
    const int hh = ch & (HHZ - 1);

    const float* g = gates + (size_t)b * N3Z + hh;
    float c = carry[(size_t)j * CHN + ch];
    const int s0 = j * CS;
    #pragma unroll 4
    for (int s = s0; s < s0 + CS; ++s) {
        const size_t go = (size_t)s * BBZ * N3Z;
        float u = g[go];
        float f = sigm(g[go + HHZ]);
        float o = sigm(g[go + 2 * HHZ]);
        c = f * c + (1.0f - f) * u;
        const size_t xo = (size_t)s * CHN + ch;
        float h = o * tanhf(c) + (1.0f - o) * xin[xo];
        hout_h[xo] = __float2half_rn(h);
    }
}

// Pass 3b (layer 2): xin fp16 (h1), h out fp32 (final output).
__global__ void scan_pass3_b(const float* __restrict__ gates,
                             const __half* __restrict__ xin,
                             const float* __restrict__ carry,
                             float* __restrict__ hout)
{
    const int idx = blockIdx.x * blockDim.x + threadIdx.x;
    const int ch = idx & (CHN - 1);
    const int j  = idx >> 13;
    const int b  = ch >> 10;
    const int hh = ch & (HHZ - 1);

    const float* g = gates + (size_t)b * N3Z + hh;
    float c = carry[(size_t)j * CHN + ch];
    const int s0 = j * CS;
    #pragma unroll 4
    for (int s = s0; s < s0 + CS; ++s) {
        const size_t go = (size_t)s * BBZ * N3Z;
        float u = g[go];
        float f = sigm(g[go + HHZ]);
        float o = sigm(g[go + 2 * HHZ]);
        c = f * c + (1.0f - f) * u;
        const size_t xo = (size_t)s * CHN + ch;
        float xv = __half2float(xin[xo]);
        hout[xo] = o * tanhf(c) + (1.0f - o) * xv;
    }
}

// ---------------- launch ---------------------------------------------------
extern "C" void kernel_launch(void* const* d_in, const int* in_sizes, int n_in,
                              void* d_out, int out_size)
{
    const float* x  = (const float*)d_in[0];
    const float* h0 = (const float*)d_in[1];
    const float* W1 = (const float*)d_in[2];
    const float* b1 = (const float*)d_in[3];
    const float* W2 = (const float*)d_in[4];
    const float* b2 = (const float*)d_in[5];

    float* out    = (float*)d_out;
    float* h2     = out;
    float* hidden = out + (size_t)SSZ * CHN;

    float *gates, *sP, *sE, *sC;
    __half *Ah, *W1h, *W2h;
    cudaGetSymbolAddress((void**)&gates, g_gates);
    cudaGetSymbolAddress((void**)&Ah,    g_Ah);
    cudaGetSymbolAddress((void**)&W1h,   g_W1h);
    cudaGetSymbolAddress((void**)&W2h,   g_W2h);
    cudaGetSymbolAddress((void**)&sP,    g_scanP);
    cudaGetSymbolAddress((void**)&sE,    g_scanE);
    cudaGetSymbolAddress((void**)&sC,    g_scanC);

    cudaFuncSetAttribute(gemm_mma2, cudaFuncAttributeMaxDynamicSharedMemorySize,
                         SMEM_NEED);

    const int ncv = (MMZ * KKZ / 4) / 256;
    dim3 wgrid(N3Z / 32, KKZ / 32), wblk(32, 8);
    dim3 ggrid(N3Z / BN, MMZ / BM);          // 24 x 128
    const int pgrid = (NC * CHN) / 256;      // 2048 blocks
    const int cgrid = CHN / 256;             // 32 blocks

    // weight prep
    wtrans_kernel<<<wgrid, wblk>>>(W1, W1h);
    wtrans_kernel<<<wgrid, wblk>>>(W2, W2h);

    // Layer 1
    tofp16_kernel<<<ncv, 256>>>(x, Ah);
    gemm_mma2<<<ggrid, 256, SMEM_NEED>>>(Ah, W1h, b1, gates);
    scan_pass1<<<pgrid, 256>>>(gates, sP, sE);
    scan_pass2<<<cgrid, 256>>>(sP, sE, h0, sC, hidden);
    scan_pass3_a<<<pgrid, 256>>>(gates, x, sC, Ah);     // h1 -> fp16 in-place of A

    // Layer 2
    gemm_mma2<<<ggrid, 256, SMEM_NEED>>>(Ah, W2h, b2, gates);
    scan_pass1<<<pgrid, 256>>>(gates, sP, sE);
    scan_pass2<<<cgrid, 256>>>(sP, sE, h0 + CHN, sC, hidden + CHN);
    scan_pass3_b<<<pgrid, 256>>>(gates, Ah, sC, h2);
}

// round 11
// speedup vs baseline: 8.3342x; 1.2298x over previous
#include <cuda_runtime.h>
#include <cuda_fp16.h>
#include <cstdint>
#include <cstddef>

// Problem constants
#define SSZ  4096
#define BBZ  8
#define HHZ  1024
#define N3Z  3072
#define MMZ  32768          // S*B
#define KKZ  1024
#define CHN  (BBZ * HHZ)    // 8192 channels
#define CS   64             // scan chunk length
#define NC   (SSZ / CS)     // 64 chunks

// ---------------- device-global scratch (no allocations allowed) ----------
// Gate arrays: logically [S][CHN] since (s*8+b)*1024+hh == s*CHN + ch
__device__ float  g_gU[(size_t)MMZ * HHZ];      // 134 MB (u, fp32)
__device__ __half g_gF[(size_t)MMZ * HHZ];      // 64 MB (sigmoid(f), fp16)
__device__ __half g_gO[(size_t)MMZ * HHZ];      // 64 MB (sigmoid(o), fp16)
__device__ __half g_Ah[(size_t)MMZ * KKZ];      // 64 MB (x fp16, then h1 fp16)
__device__ __half g_W1h[(size_t)N3Z * KKZ];     // 6 MB
__device__ __half g_W2h[(size_t)N3Z * KKZ];     // 6 MB
__device__ float  g_scanP[(size_t)NC * CHN];
__device__ float  g_scanE[(size_t)NC * CHN];
__device__ float  g_scanC[(size_t)NC * CHN];

// ---------------- PTX helpers ---------------------------------------------
__device__ __forceinline__ uint32_t smem_u32(const void* p) {
    uint32_t a;
    asm("{ .reg .u64 t; cvta.to.shared.u64 t, %1; cvt.u32.u64 %0, t; }"
        : "=r"(a) : "l"(p));
    return a;
}

#define CP16(saddr, gptr) \
    asm volatile("cp.async.cg.shared.global [%0], [%1], 16;" \
                 :: "r"(saddr), "l"(gptr))
#define CP_COMMIT() asm volatile("cp.async.commit_group;" ::: "memory")
#define CP_WAIT(n)  asm volatile("cp.async.wait_group %0;" :: "n"(n) : "memory")

#define LDSM4(r0, r1, r2, r3, addr) \
    asm volatile("ldmatrix.sync.aligned.m8n8.x4.shared.b16 {%0,%1,%2,%3}, [%4];" \
                 : "=r"(r0), "=r"(r1), "=r"(r2), "=r"(r3) : "r"(addr))

#define MMAF16(d, a, b0, b1) \
    asm volatile("mma.sync.aligned.m16n8k16.row.col.f32.f16.f16.f32 " \
                 "{%0,%1,%2,%3},{%4,%5,%6,%7},{%8,%9},{%0,%1,%2,%3};" \
                 : "+f"((d)[0]), "+f"((d)[1]), "+f"((d)[2]), "+f"((d)[3]) \
                 : "r"((a)[0]), "r"((a)[1]), "r"((a)[2]), "r"((a)[3]), \
                   "r"(b0), "r"(b1))

__device__ __forceinline__ float sigm(float v) {
    return 1.0f / (1.0f + __expf(-v));
}
// inf-safe fast tanh: copysign(1 - 2/(exp(2|x|)+1), x)
__device__ __forceinline__ float tanh_fast(float x) {
    float e = __expf(2.0f * fabsf(x));      // overflows to +inf safely
    float t = 1.0f - 2.0f / (e + 1.0f);
    return copysignf(t, x);
}

// ---------------- GEMM: 256x128 CTA, fp16 1-pass, 4-stage cp.async --------
#define BM 256
#define BN 128
#define BK 64
#define NT (KKZ / BK)                 // 16
#define OFF_A  0                      // A: 256 x 128B = 32 KB
#define OFF_B  32768                  // W: 128 x 128B = 16 KB
#define STAGE_BYTES 49152             // 48 KB
#define NSTG 4
#define STAGES_OFF 1024
#define SMEM_NEED (STAGES_OFF + NSTG * STAGE_BYTES + 1024)

__device__ __forceinline__ uint32_t swz_rs(uint32_t row, uint32_t seg) {
    return row * 128u + (((seg ^ row) & 7u) << 4);
}

__global__ void __launch_bounds__(256, 1)
gemm_mma2(const __half* __restrict__ Ah, const __half* __restrict__ Wh,
          const float* __restrict__ bias,
          float* __restrict__ gU, __half* __restrict__ gF, __half* __restrict__ gO)
{
    extern __shared__ char smraw[];
    const uint32_t sb0 = smem_u32(smraw);
    const uint32_t sb  = (sb0 + 1023u) & ~1023u;
    char* smp = smraw + (sb - sb0);

    const int tid  = threadIdx.x;
    const int wid  = tid >> 5;
    const int lane = tid & 31;
    const int wm   = wid >> 1;            // 0..3 (m)
    const int wn   = wid & 1;             // 0..1 (n)
    const int bn   = blockIdx.x * BN;
    const int bm   = blockIdx.y * BM;

    if (tid < 128) ((float*)smp)[tid] = bias[bn + tid];

    auto load_stage = [&](int t, int st) {
        const int k0 = t * BK;
        const uint32_t s0 = sb + STAGES_OFF + st * STAGE_BYTES;
        #pragma unroll
        for (int r = 0; r < 8; ++r) {
            const int idx = tid + r * 256;
            const uint32_t row = idx >> 3, seg = idx & 7;
            CP16(s0 + OFF_A + swz_rs(row, seg),
                 Ah + (size_t)(bm + row) * KKZ + k0 + seg * 8);
        }
        #pragma unroll
        for (int r = 0; r < 4; ++r) {
            const int idx = tid + r * 256;
            const uint32_t row = idx >> 3, seg = idx & 7;
            CP16(s0 + OFF_B + swz_rs(row, seg),
                 Wh + (size_t)(bn + row) * KKZ + k0 + seg * 8);
        }
    };

    const uint32_t a_row = (uint32_t)(wm * 64) + (lane & 15);
    const uint32_t a_kh  = (uint32_t)(lane >> 4);
    const uint32_t b_row = (uint32_t)(wn * 64) + (lane & 7) + ((lane >> 4) << 3);
    const uint32_t b_kh  = (uint32_t)((lane >> 3) & 1);

    float acc[4][8][4];
    #pragma unroll
    for (int mi = 0; mi < 4; ++mi)
        #pragma unroll
        for (int ni = 0; ni < 8; ++ni)
            #pragma unroll
            for (int j = 0; j < 4; ++j) acc[mi][ni][j] = 0.0f;

    load_stage(0, 0); CP_COMMIT();
    load_stage(1, 1); CP_COMMIT();
    load_stage(2, 2); CP_COMMIT();

    #pragma unroll 1
    for (int t = 0; t < NT; ++t) {
        CP_WAIT(2);
        __syncthreads();
        if (t + 3 < NT) load_stage(t + 3, (t + 3) & (NSTG - 1));
        CP_COMMIT();

        const uint32_t s0 = sb + STAGES_OFF + (t & (NSTG - 1)) * STAGE_BYTES;

        #pragma unroll
        for (int ks = 0; ks < 4; ++ks) {
            const uint32_t a_seg = (uint32_t)(ks * 2) + a_kh;
            const uint32_t b_seg = (uint32_t)(ks * 2) + b_kh;
            uint32_t af[4][4], bf[4][4];
            #pragma unroll
            for (int mi = 0; mi < 4; ++mi) {
                const uint32_t so = swz_rs(a_row + mi * 16, a_seg);
                LDSM4(af[mi][0], af[mi][1], af[mi][2], af[mi][3], s0 + OFF_A + so);
            }
            #pragma unroll
            for (int nb = 0; nb < 4; ++nb) {
                const uint32_t so = swz_rs(b_row + nb * 16, b_seg);
                LDSM4(bf[nb][0], bf[nb][1], bf[nb][2], bf[nb][3], s0 + OFF_B + so);
            }
            #pragma unroll
            for (int mi = 0; mi < 4; ++mi)
                #pragma unroll
                for (int ni = 0; ni < 8; ++ni)
                    MMAF16(acc[mi][ni], af[mi],
                           bf[ni >> 1][2 * (ni & 1)], bf[ni >> 1][2 * (ni & 1) + 1]);
        }
    }

    // ---- gate-typed epilogue ----
    // blockIdx.x in [0,24): >>3 selects gate region (0=u,1=f,2=o),
    // &7 selects 128-col block within the H=1024 gate.
    const int creg = blockIdx.x >> 3;
    const int cb   = (blockIdx.x & 7) * 128;
    const float* bsm = (const float*)smp;
    #pragma unroll
    for (int mi = 0; mi < 4; ++mi) {
        const int r0 = bm + wm * 64 + mi * 16 + (lane >> 2);
        #pragma unroll
        for (int ni = 0; ni < 8; ++ni) {
            const int cl = wn * 64 + ni * 8 + (lane & 3) * 2;
            const float b0 = bsm[cl], b1 = bsm[cl + 1];
            float a0 = acc[mi][ni][0] + b0, a1 = acc[mi][ni][1] + b1;
            float a2 = acc[mi][ni][2] + b0, a3 = acc[mi][ni][3] + b1;
            const size_t o0 = (size_t)r0 * HHZ + cb + cl;
            const size_t o1 = (size_t)(r0 + 8) * HHZ + cb + cl;
            if (creg == 0) {
                *(float2*)(gU + o0) = make_float2(a0, a1);
                *(float2*)(gU + o1) = make_float2(a2, a3);
            } else {
                __half* dst = (creg == 1) ? gF : gO;
                __half2 v0 = __floats2half2_rn(sigm(a0), sigm(a1));
                __half2 v1 = __floats2half2_rn(sigm(a2), sigm(a3));
                *(__half2*)(dst + o0) = v0;
                *(__half2*)(dst + o1) = v1;
            }
        }
    }
}

// ---------------- fp32 -> fp16 convert -------------------------------------
__global__ void tofp16_kernel(const float* __restrict__ in,
                              __half* __restrict__ out)
{
    size_t i = (size_t)blockIdx.x * blockDim.x + threadIdx.x;
    float4 v = ((const float4*)in)[i];
    ((__half2*)out)[2 * i + 0] = __floats2half2_rn(v.x, v.y);
    ((__half2*)out)[2 * i + 1] = __floats2half2_rn(v.z, v.w);
}

// ---------------- W[K,N] -> Wt[N,K] transpose + fp16 convert ---------------
__global__ void wtrans_kernel(const float* __restrict__ W,
                              __half* __restrict__ hi)
{
    __shared__ float t[32][33];
    const int n0 = blockIdx.x * 32, k0 = blockIdx.y * 32;
    const int tx = threadIdx.x, ty = threadIdx.y;   // 32 x 8
    #pragma unroll
    for (int i = 0; i < 4; ++i)
        t[ty + i*8][tx] = W[(size_t)(k0 + ty + i*8) * N3Z + n0 + tx];
    __syncthreads();
    #pragma unroll
    for (int i = 0; i < 4; ++i) {
        float v = t[tx][ty + i*8];
        hi[(size_t)(n0 + ty + i*8) * KKZ + k0 + tx] = __float2half_rn(v);
    }
}

// ---------------- chunked SRU scan (4 channels / thread) --------------------
__device__ __forceinline__ float4 ldh4(const __half* p) {
    uint2 raw = *(const uint2*)p;
    __half2 h0 = *(__half2*)&raw.x;
    __half2 h1 = *(__half2*)&raw.y;
    float2 f0 = __half22float2(h0);
    float2 f1 = __half22float2(h1);
    return make_float4(f0.x, f0.y, f1.x, f1.y);
}
__device__ __forceinline__ void sth4(__half* p, float4 v) {
    uint2 raw;
    *(__half2*)&raw.x = __floats2half2_rn(v.x, v.y);
    *(__half2*)&raw.y = __floats2half2_rn(v.z, v.w);
    *(uint2*)p = raw;
}

// Pass 1: per (4-channel group, chunk) partial scan from 0; prod(f), endpoint.
__global__ void scan_pass1(const float* __restrict__ gU, const __half* __restrict__ gF,
                           float* __restrict__ P, float* __restrict__ E)
{
    const int idx = blockIdx.x * blockDim.x + threadIdx.x;   // 0..NC*CHN/4-1
    const int chv = idx & (CHN / 4 - 1);
    const int j   = idx >> 11;
    const int ch  = chv << 2;

    float4 c = make_float4(0.f, 0.f, 0.f, 0.f);
    float4 p = make_float4(1.f, 1.f, 1.f, 1.f);
    const int s0 = j * CS;
    #pragma unroll 4
    for (int s = s0; s < s0 + CS; ++s) {
        const size_t off = (size_t)s * CHN + ch;
        float4 u = *(const float4*)(gU + off);
        float4 f = ldh4(gF + off);
        c.x = f.x * c.x + (1.f - f.x) * u.x;  p.x *= f.x;
        c.y = f.y * c.y + (1.f - f.y) * u.y;  p.y *= f.y;
        c.z = f.z * c.z + (1.f - f.z) * u.z;  p.z *= f.z;
        c.w = f.w * c.w + (1.f - f.w) * u.w;  p.w *= f.w;
    }
    *(float4*)(P + (size_t)j * CHN + ch) = p;
    *(float4*)(E + (size_t)j * CHN + ch) = c;
}

// Pass 2: sequential carry propagation across chunks (exact).
__global__ void scan_pass2(const float* __restrict__ P, const float* __restrict__ E,
                           const float* __restrict__ c0,
                           float* __restrict__ carry, float* __restrict__ clast)
{
    const int ch = (blockIdx.x * blockDim.x + threadIdx.x) << 2;  // 4-ch groups
    float4 c = *(const float4*)(c0 + ch);
    #pragma unroll 8
    for (int j = 0; j < NC; ++j) {
        const size_t off = (size_t)j * CHN + ch;
        *(float4*)(carry + off) = c;
        float4 e = *(const float4*)(E + off);
        float4 p = *(const float4*)(P + off);
        c.x = e.x + p.x * c.x;  c.y = e.y + p.y * c.y;
        c.z = e.z + p.z * c.z;  c.w = e.w + p.w * c.w;
    }
    *(float4*)(clast + ch) = c;
}

// Pass 3, layer 1: x fp32, h out fp16 (becomes next layer's A).
__global__ void scan_pass3_a(const float* __restrict__ gU, const __half* __restrict__ gF,
                             const __half* __restrict__ gO,
                             const float* __restrict__ xin,
                             const float* __restrict__ carry,
                             __half* __restrict__ hout_h)
{
    const int idx = blockIdx.x * blockDim.x + threadIdx.x;
    const int chv = idx & (CHN / 4 - 1);
    const int j   = idx >> 11;
    const int ch  = chv << 2;

    float4 c = *(const float4*)(carry + (size_t)j * CHN + ch);
    const int s0 = j * CS;
    #pragma unroll 4
    for (int s = s0; s < s0 + CS; ++s) {
        const size_t off = (size_t)s * CHN + ch;
        float4 u = *(const float4*)(gU + off);
        float4 f = ldh4(gF + off);
        float4 o = ldh4(gO + off);
        float4 x = *(const float4*)(xin + off);
        c.x = f.x * c.x + (1.f - f.x) * u.x;
        c.y = f.y * c.y + (1.f - f.y) * u.y;
        c.z = f.z * c.z + (1.f - f.z) * u.z;
        c.w = f.w * c.w + (1.f - f.w) * u.w;
        float4 h;
        h.x = o.x * tanh_fast(c.x) + (1.f - o.x) * x.x;
        h.y = o.y * tanh_fast(c.y) + (1.f - o.y) * x.y;
        h.z = o.z * tanh_fast(c.z) + (1.f - o.z) * x.z;
        h.w = o.w * tanh_fast(c.w) + (1.f - o.w) * x.w;
        sth4(hout_h + off, h);
    }
}

// Pass 3, layer 2: x fp16 (h1), h out fp32 (final output).
__global__ void scan_pass3_b(const float* __restrict__ gU, const __half* __restrict__ gF,
                             const __half* __restrict__ gO,
                             const __half* __restrict__ xin,
                             const float* __restrict__ carry,
                             float* __restrict__ hout)
{
    const int idx = blockIdx.x * blockDim.x + threadIdx.x;
    const int chv = idx & (CHN / 4 - 1);
    const int j   = idx >> 11;
    const int ch  = chv << 2;

    float4 c = *(const float4*)(carry + (size_t)j * CHN + ch);
    const int s0 = j * CS;
    #pragma unroll 4
    for (int s = s0; s < s0 + CS; ++s) {
        const size_t off = (size_t)s * CHN + ch;
        float4 u = *(const float4*)(gU + off);
        float4 f = ldh4(gF + off);
        float4 o = ldh4(gO + off);
        float4 x = ldh4(xin + off);
        c.x = f.x * c.x + (1.f - f.x) * u.x;
        c.y = f.y * c.y + (1.f - f.y) * u.y;
        c.z = f.z * c.z + (1.f - f.z) * u.z;
        c.w = f.w * c.w + (1.f - f.w) * u.w;
        float4 h;
        h.x = o.x * tanh_fast(c.x) + (1.f - o.x) * x.x;
        h.y = o.y * tanh_fast(c.y) + (1.f - o.y) * x.y;
        h.z = o.z * tanh_fast(c.z) + (1.f - o.z) * x.z;
        h.w = o.w * tanh_fast(c.w) + (1.f - o.w) * x.w;
        *(float4*)(hout + off) = h;
    }
}

// ---------------- launch ---------------------------------------------------
extern "C" void kernel_launch(void* const* d_in, const int* in_sizes, int n_in,
                              void* d_out, int out_size)
{
    const float* x  = (const float*)d_in[0];
    const float* h0 = (const float*)d_in[1];
    const float* W1 = (const float*)d_in[2];
    const float* b1 = (const float*)d_in[3];
    const float* W2 = (const float*)d_in[4];
    const float* b2 = (const float*)d_in[5];

    float* out    = (float*)d_out;
    float* h2     = out;
    float* hidden = out + (size_t)SSZ * CHN;

    float *gU, *sP, *sE, *sC;
    __half *gF, *gO, *Ah, *W1h, *W2h;
    cudaGetSymbolAddress((void**)&gU,  g_gU);
    cudaGetSymbolAddress((void**)&gF,  g_gF);
    cudaGetSymbolAddress((void**)&gO,  g_gO);
    cudaGetSymbolAddress((void**)&Ah,  g_Ah);
    cudaGetSymbolAddress((void**)&W1h, g_W1h);
    cudaGetSymbolAddress((void**)&W2h, g_W2h);
    cudaGetSymbolAddress((void**)&sP,  g_scanP);
    cudaGetSymbolAddress((void**)&sE,  g_scanE);
    cudaGetSymbolAddress((void**)&sC,  g_scanC);

    cudaFuncSetAttribute(gemm_mma2, cudaFuncAttributeMaxDynamicSharedMemorySize,
                         SMEM_NEED);

    const int ncv = (MMZ * KKZ / 4) / 256;
    dim3 wgrid(N3Z / 32, KKZ / 32), wblk(32, 8);
    dim3 ggrid(N3Z / BN, MMZ / BM);              // 24 x 128
    const int pgrid = (NC * CHN / 4) / 256;      // 512 blocks
    const int cgrid = (CHN / 4) / 256;           // 8 blocks

    // weight prep
    wtrans_kernel<<<wgrid, wblk>>>(W1, W1h);
    wtrans_kernel<<<wgrid, wblk>>>(W2, W2h);

    // Layer 1
    tofp16_kernel<<<ncv, 256>>>(x, Ah);
    gemm_mma2<<<ggrid, 256, SMEM_NEED>>>(Ah, W1h, b1, gU, gF, gO);
    scan_pass1<<<pgrid, 256>>>(gU, gF, sP, sE);
    scan_pass2<<<cgrid, 256>>>(sP, sE, h0, sC, hidden);
    scan_pass3_a<<<pgrid, 256>>>(gU, gF, gO, x, sC, Ah);   // h1 -> fp16 over A

    // Layer 2
    gemm_mma2<<<ggrid, 256, SMEM_NEED>>>(Ah, W2h, b2, gU, gF, gO);
    scan_pass1<<<pgrid, 256>>>(gU, gF, sP, sE);
    scan_pass2<<<cgrid, 256>>>(sP, sE, h0 + CHN, sC, hidden + CHN);
    scan_pass3_b<<<pgrid, 256>>>(gU, gF, gO, Ah, sC, h2);
}

// round 13
// speedup vs baseline: 9.6571x; 1.1587x over previous
#include <cuda_runtime.h>
#include <cuda_fp16.h>
#include <cstdint>
#include <cstddef>

// Problem constants
#define SSZ  4096
#define BBZ  8
#define HHZ  1024
#define N3Z  3072
#define MMZ  32768          // S*B
#define KKZ  1024
#define CHN  (BBZ * HHZ)    // 8192 channels
#define CS   64             // scan chunk length
#define NC   (SSZ / CS)     // 64 chunks

// ---------------- device-global scratch (no allocations allowed) ----------
// Gate arrays: logically [S][CHN] since (s*8+b)*1024+hh == s*CHN + ch
__device__ float  g_gU[(size_t)MMZ * HHZ];      // 134 MB (u, fp32)
__device__ __half g_gF[(size_t)MMZ * HHZ];      // 64 MB (sigmoid(f), fp16)
__device__ __half g_gO[(size_t)MMZ * HHZ];      // 64 MB (sigmoid(o), fp16)
__device__ __half g_Ah[(size_t)MMZ * KKZ];      // 64 MB (x fp16, then h1 fp16)
__device__ __half g_W1h[(size_t)N3Z * KKZ];     // 6 MB
__device__ __half g_W2h[(size_t)N3Z * KKZ];     // 6 MB
__device__ float  g_scanP[(size_t)NC * CHN];
__device__ float  g_scanE[(size_t)NC * CHN];
__device__ float  g_scanC[(size_t)NC * CHN];

// ---------------- PTX helpers ---------------------------------------------
__device__ __forceinline__ uint32_t smem_u32(const void* p) {
    uint32_t a;
    asm("{ .reg .u64 t; cvta.to.shared.u64 t, %1; cvt.u32.u64 %0, t; }"
        : "=r"(a) : "l"(p));
    return a;
}

#define CP16(saddr, gptr) \
    asm volatile("cp.async.cg.shared.global [%0], [%1], 16;" \
                 :: "r"(saddr), "l"(gptr))
#define CP_COMMIT() asm volatile("cp.async.commit_group;" ::: "memory")
#define CP_WAIT(n)  asm volatile("cp.async.wait_group %0;" :: "n"(n) : "memory")

#define LDSM4(r0, r1, r2, r3, addr) \
    asm volatile("ldmatrix.sync.aligned.m8n8.x4.shared.b16 {%0,%1,%2,%3}, [%4];" \
                 : "=r"(r0), "=r"(r1), "=r"(r2), "=r"(r3) : "r"(addr))

#define MMAF16(d, a, b0, b1) \
    asm volatile("mma.sync.aligned.m16n8k16.row.col.f32.f16.f16.f32 " \
                 "{%0,%1,%2,%3},{%4,%5,%6,%7},{%8,%9},{%0,%1,%2,%3};" \
                 : "+f"((d)[0]), "+f"((d)[1]), "+f"((d)[2]), "+f"((d)[3]) \
                 : "r"((a)[0]), "r"((a)[1]), "r"((a)[2]), "r"((a)[3]), \
                   "r"(b0), "r"(b1))

__device__ __forceinline__ float sigm(float v) {
    return 1.0f / (1.0f + __expf(-v));
}
// inf-safe fast tanh: copysign(1 - 2/(exp(2|x|)+1), x)
__device__ __forceinline__ float tanh_fast(float x) {
    float e = __expf(2.0f * fabsf(x));      // overflows to +inf safely
    float t = 1.0f - 2.0f / (e + 1.0f);
    return copysignf(t, x);
}

// ---------------- GEMM: 128x128 CTA, 2 CTAs/SM, 3-stage cp.async ----------
#define BM 128
#define BN 128
#define BK 64
#define NT (KKZ / BK)                 // 16
#define OFF_A  0                      // A: 128 x 128B = 16 KB
#define OFF_B  16384                  // W: 128 x 128B = 16 KB
#define STAGE_BYTES 32768             // 32 KB
#define NSTG 3
#define STAGES_OFF 1024
#define SMEM_NEED (STAGES_OFF + NSTG * STAGE_BYTES + 1024)   // ~100 KB

__device__ __forceinline__ uint32_t swz_rs(uint32_t row, uint32_t seg) {
    return row * 128u + (((seg ^ row) & 7u) << 4);
}

__global__ void __launch_bounds__(256, 2)
gemm_mma2(const __half* __restrict__ Ah, const __half* __restrict__ Wh,
          const float* __restrict__ bias,
          float* __restrict__ gU, __half* __restrict__ gF, __half* __restrict__ gO)
{
    extern __shared__ char smraw[];
    const uint32_t sb0 = smem_u32(smraw);
    const uint32_t sb  = (sb0 + 1023u) & ~1023u;
    char* smp = smraw + (sb - sb0);

    const int tid  = threadIdx.x;
    const int wid  = tid >> 5;
    const int lane = tid & 31;
    const int wm   = wid >> 1;            // 0..3 (m), warp tile 32x64
    const int wn   = wid & 1;             // 0..1 (n)
    const int bn   = blockIdx.x * BN;
    const int bm   = blockIdx.y * BM;

    if (tid < 128) ((float*)smp)[tid] = bias[bn + tid];

    // loader: 8 cp16 per thread per stage (A:4, B:4)
    auto load_stage = [&](int t, int st) {
        const int k0 = t * BK;
        const uint32_t s0 = sb + STAGES_OFF + st * STAGE_BYTES;
        #pragma unroll
        for (int r = 0; r < 4; ++r) {
            const int idx = tid + r * 256;
            const uint32_t row = idx >> 3, seg = idx & 7;
            CP16(s0 + OFF_A + swz_rs(row, seg),
                 Ah + (size_t)(bm + row) * KKZ + k0 + seg * 8);
        }
        #pragma unroll
        for (int r = 0; r < 4; ++r) {
            const int idx = tid + r * 256;
            const uint32_t row = idx >> 3, seg = idx & 7;
            CP16(s0 + OFF_B + swz_rs(row, seg),
                 Wh + (size_t)(bn + row) * KKZ + k0 + seg * 8);
        }
    };

    const uint32_t a_row = (uint32_t)(wm * 32) + (lane & 15);
    const uint32_t a_kh  = (uint32_t)(lane >> 4);
    const uint32_t b_row = (uint32_t)(wn * 64) + (lane & 7) + ((lane >> 4) << 3);
    const uint32_t b_kh  = (uint32_t)((lane >> 3) & 1);

    float acc[2][8][4];
    #pragma unroll
    for (int mi = 0; mi < 2; ++mi)
        #pragma unroll
        for (int ni = 0; ni < 8; ++ni)
            #pragma unroll
            for (int j = 0; j < 4; ++j) acc[mi][ni][j] = 0.0f;

    load_stage(0, 0); CP_COMMIT();
    load_stage(1, 1); CP_COMMIT();

    #pragma unroll 1
    for (int t = 0; t < NT; ++t) {
        CP_WAIT(1);
        __syncthreads();
        if (t + 2 < NT) load_stage(t + 2, (t + 2) % NSTG);
        CP_COMMIT();                      // unconditional: group count stays exact

        const uint32_t s0 = sb + STAGES_OFF + (t % NSTG) * STAGE_BYTES;

        #pragma unroll
        for (int ks = 0; ks < 4; ++ks) {
            const uint32_t a_seg = (uint32_t)(ks * 2) + a_kh;
            const uint32_t b_seg = (uint32_t)(ks * 2) + b_kh;
            uint32_t af[2][4], bf[4][4];
            #pragma unroll
            for (int mi = 0; mi < 2; ++mi) {
                const uint32_t so = swz_rs(a_row + mi * 16, a_seg);
                LDSM4(af[mi][0], af[mi][1], af[mi][2], af[mi][3], s0 + OFF_A + so);
            }
            #pragma unroll
            for (int nb = 0; nb < 4; ++nb) {
                const uint32_t so = swz_rs(b_row + nb * 16, b_seg);
                LDSM4(bf[nb][0], bf[nb][1], bf[nb][2], bf[nb][3], s0 + OFF_B + so);
            }
            #pragma unroll
            for (int mi = 0; mi < 2; ++mi)
                #pragma unroll
                for (int ni = 0; ni < 8; ++ni)
                    MMAF16(acc[mi][ni], af[mi],
                           bf[ni >> 1][2 * (ni & 1)], bf[ni >> 1][2 * (ni & 1) + 1]);
        }
    }

    // ---- gate-typed epilogue ----
    // blockIdx.x in [0,24): >>3 selects gate (0=u,1=f,2=o), &7 -> 128-col block.
    const int creg = blockIdx.x >> 3;
    const int cb   = (blockIdx.x & 7) * 128;
    const float* bsm = (const float*)smp;
    #pragma unroll
    for (int mi = 0; mi < 2; ++mi) {
        const int r0 = bm + wm * 32 + mi * 16 + (lane >> 2);
        #pragma unroll
        for (int ni = 0; ni < 8; ++ni) {
            const int cl = wn * 64 + ni * 8 + (lane & 3) * 2;
            const float b0 = bsm[cl], b1 = bsm[cl + 1];
            float a0 = acc[mi][ni][0] + b0, a1 = acc[mi][ni][1] + b1;
            float a2 = acc[mi][ni][2] + b0, a3 = acc[mi][ni][3] + b1;
            const size_t o0 = (size_t)r0 * HHZ + cb + cl;
            const size_t o1 = (size_t)(r0 + 8) * HHZ + cb + cl;
            if (creg == 0) {
                *(float2*)(gU + o0) = make_float2(a0, a1);
                *(float2*)(gU + o1) = make_float2(a2, a3);
            } else {
                __half* dst = (creg == 1) ? gF : gO;
                *(__half2*)(dst + o0) = __floats2half2_rn(sigm(a0), sigm(a1));
                *(__half2*)(dst + o1) = __floats2half2_rn(sigm(a2), sigm(a3));
            }
        }
    }
}

// ---------------- fp32 -> fp16 convert -------------------------------------
__global__ void tofp16_kernel(const float* __restrict__ in,
                              __half* __restrict__ out)
{
    size_t i = (size_t)blockIdx.x * blockDim.x + threadIdx.x;
    float4 v = ((const float4*)in)[i];
    ((__half2*)out)[2 * i + 0] = __floats2half2_rn(v.x, v.y);
    ((__half2*)out)[2 * i + 1] = __floats2half2_rn(v.z, v.w);
}

// ---------------- W[K,N] -> Wt[N,K] transpose + fp16 convert ---------------
__global__ void wtrans_kernel(const float* __restrict__ W,
                              __half* __restrict__ hi)
{
    __shared__ float t[32][33];
    const int n0 = blockIdx.x * 32, k0 = blockIdx.y * 32;
    const int tx = threadIdx.x, ty = threadIdx.y;   // 32 x 8
    #pragma unroll
    for (int i = 0; i < 4; ++i)
        t[ty + i*8][tx] = W[(size_t)(k0 + ty + i*8) * N3Z + n0 + tx];
    __syncthreads();
    #pragma unroll
    for (int i = 0; i < 4; ++i) {
        float v = t[tx][ty + i*8];
        hi[(size_t)(n0 + ty + i*8) * KKZ + k0 + tx] = __float2half_rn(v);
    }
}

// ---------------- chunked SRU scan (4 channels / thread) --------------------
__device__ __forceinline__ float4 ldh4(const __half* p) {
    uint2 raw = *(const uint2*)p;
    __half2 h0 = *(__half2*)&raw.x;
    __half2 h1 = *(__half2*)&raw.y;
    float2 f0 = __half22float2(h0);
    float2 f1 = __half22float2(h1);
    return make_float4(f0.x, f0.y, f1.x, f1.y);
}
__device__ __forceinline__ void sth4(__half* p, float4 v) {
    uint2 raw;
    *(__half2*)&raw.x = __floats2half2_rn(v.x, v.y);
    *(__half2*)&raw.y = __floats2half2_rn(v.z, v.w);
    *(uint2*)p = raw;
}

// Pass 1: per (4-channel group, chunk) partial scan from 0; prod(f), endpoint.
__global__ void scan_pass1(const float* __restrict__ gU, const __half* __restrict__ gF,
                           float* __restrict__ P, float* __restrict__ E)
{
    const int idx = blockIdx.x * blockDim.x + threadIdx.x;   // 0..NC*CHN/4-1
    const int chv = idx & (CHN / 4 - 1);
    const int j   = idx >> 11;
    const int ch  = chv << 2;

    float4 c = make_float4(0.f, 0.f, 0.f, 0.f);
    float4 p = make_float4(1.f, 1.f, 1.f, 1.f);
    const int s0 = j * CS;
    #pragma unroll 4
    for (int s = s0; s < s0 + CS; ++s) {
        const size_t off = (size_t)s * CHN + ch;
        float4 u = *(const float4*)(gU + off);
        float4 f = ldh4(gF + off);
        c.x = f.x * c.x + (1.f - f.x) * u.x;  p.x *= f.x;
        c.y = f.y * c.y + (1.f - f.y) * u.y;  p.y *= f.y;
        c.z = f.z * c.z + (1.f - f.z) * u.z;  p.z *= f.z;
        c.w = f.w * c.w + (1.f - f.w) * u.w;  p.w *= f.w;
    }
    *(float4*)(P + (size_t)j * CHN + ch) = p;
    *(float4*)(E + (size_t)j * CHN + ch) = c;
}

// Pass 2: sequential carry propagation across chunks (exact).
__global__ void scan_pass2(const float* __restrict__ P, const float* __restrict__ E,
                           const float* __restrict__ c0,
                           float* __restrict__ carry, float* __restrict__ clast)
{
    const int ch = (blockIdx.x * blockDim.x + threadIdx.x) << 2;  // 4-ch groups
    float4 c = *(const float4*)(c0 + ch);
    #pragma unroll 8
    for (int j = 0; j < NC; ++j) {
        const size_t off = (size_t)j * CHN + ch;
        *(float4*)(carry + off) = c;
        float4 e = *(const float4*)(E + off);
        float4 p = *(const float4*)(P + off);
        c.x = e.x + p.x * c.x;  c.y = e.y + p.y * c.y;
        c.z = e.z + p.z * c.z;  c.w = e.w + p.w * c.w;
    }
    *(float4*)(clast + ch) = c;
}

// Pass 3, layer 1: x fp32, h out fp16 (becomes next layer's A).
__global__ void scan_pass3_a(const float* __restrict__ gU, const __half* __restrict__ gF,
                             const __half* __restrict__ gO,
                             const float* __restrict__ xin,
                             const float* __restrict__ carry,
                             __half* __restrict__ hout_h)
{
    const int idx = blockIdx.x * blockDim.x + threadIdx.x;
    const int chv = idx & (CHN / 4 - 1);
    const int j   = idx >> 11;
    const int ch  = chv << 2;

    float4 c = *(const float4*)(carry + (size_t)j * CHN + ch);
    const int s0 = j * CS;
    #pragma unroll 4
    for (int s = s0; s < s0 + CS; ++s) {
        const size_t off = (size_t)s * CHN + ch;
        float4 u = *(const float4*)(gU + off);
        float4 f = ldh4(gF + off);
        float4 o = ldh4(gO + off);
        float4 x = *(const float4*)(xin + off);
        c.x = f.x * c.x + (1.f - f.x) * u.x;
        c.y = f.y * c.y + (1.f - f.y) * u.y;
        c.z = f.z * c.z + (1.f - f.z) * u.z;
        c.w = f.w * c.w + (1.f - f.w) * u.w;
        float4 h;
        h.x = o.x * tanh_fast(c.x) + (1.f - o.x) * x.x;
        h.y = o.y * tanh_fast(c.y) + (1.f - o.y) * x.y;
        h.z = o.z * tanh_fast(c.z) + (1.f - o.z) * x.z;
        h.w = o.w * tanh_fast(c.w) + (1.f - o.w) * x.w;
        sth4(hout_h + off, h);
    }
}

// Pass 3, layer 2: x fp16 (h1), h out fp32 (final output).
__global__ void scan_pass3_b(const float* __restrict__ gU, const __half* __restrict__ gF,
                             const __half* __restrict__ gO,
                             const __half* __restrict__ xin,
                             const float* __restrict__ carry,
                             float* __restrict__ hout)
{
    const int idx = blockIdx.x * blockDim.x + threadIdx.x;
    const int chv = idx & (CHN / 4 - 1);
    const int j   = idx >> 11;
    const int ch  = chv << 2;

    float4 c = *(const float4*)(carry + (size_t)j * CHN + ch);
    const int s0 = j * CS;
    #pragma unroll 4
    for (int s = s0; s < s0 + CS; ++s) {
        const size_t off = (size_t)s * CHN + ch;
        float4 u = *(const float4*)(gU + off);
        float4 f = ldh4(gF + off);
        float4 o = ldh4(gO + off);
        float4 x = ldh4(xin + off);
        c.x = f.x * c.x + (1.f - f.x) * u.x;
        c.y = f.y * c.y + (1.f - f.y) * u.y;
        c.z = f.z * c.z + (1.f - f.z) * u.z;
        c.w = f.w * c.w + (1.f - f.w) * u.w;
        float4 h;
        h.x = o.x * tanh_fast(c.x) + (1.f - o.x) * x.x;
        h.y = o.y * tanh_fast(c.y) + (1.f - o.y) * x.y;
        h.z = o.z * tanh_fast(c.z) + (1.f - o.z) * x.z;
        h.w = o.w * tanh_fast(c.w) + (1.f - o.w) * x.w;
        *(float4*)(hout + off) = h;
    }
}

// ---------------- launch ---------------------------------------------------
extern "C" void kernel_launch(void* const* d_in, const int* in_sizes, int n_in,
                              void* d_out, int out_size)
{
    const float* x  = (const float*)d_in[0];
    const float* h0 = (const float*)d_in[1];
    const float* W1 = (const float*)d_in[2];
    const float* b1 = (const float*)d_in[3];
    const float* W2 = (const float*)d_in[4];
    const float* b2 = (const float*)d_in[5];

    float* out    = (float*)d_out;
    float* h2     = out;
    float* hidden = out + (size_t)SSZ * CHN;

    float *gU, *sP, *sE, *sC;
    __half *gF, *gO, *Ah, *W1h, *W2h;
    cudaGetSymbolAddress((void**)&gU,  g_gU);
    cudaGetSymbolAddress((void**)&gF,  g_gF);
    cudaGetSymbolAddress((void**)&gO,  g_gO);
    cudaGetSymbolAddress((void**)&Ah,  g_Ah);
    cudaGetSymbolAddress((void**)&W1h, g_W1h);
    cudaGetSymbolAddress((void**)&W2h, g_W2h);
    cudaGetSymbolAddress((void**)&sP,  g_scanP);
    cudaGetSymbolAddress((void**)&sE,  g_scanE);
    cudaGetSymbolAddress((void**)&sC,  g_scanC);

    cudaFuncSetAttribute(gemm_mma2, cudaFuncAttributeMaxDynamicSharedMemorySize,
                         SMEM_NEED);

    const int ncv = (MMZ * KKZ / 4) / 256;
    dim3 wgrid(N3Z / 32, KKZ / 32), wblk(32, 8);
    dim3 ggrid(N3Z / BN, MMZ / BM);              // 24 x 256 = 6144 CTAs
    const int pgrid = (NC * CHN / 4) / 256;      // 512 blocks
    const int cgrid = (CHN / 4) / 256;           // 8 blocks

    // weight prep
    wtrans_kernel<<<wgrid, wblk>>>(W1, W1h);
    wtrans_kernel<<<wgrid, wblk>>>(W2, W2h);

    // Layer 1
    tofp16_kernel<<<ncv, 256>>>(x, Ah);
    gemm_mma2<<<ggrid, 256, SMEM_NEED>>>(Ah, W1h, b1, gU, gF, gO);
    scan_pass1<<<pgrid, 256>>>(gU, gF, sP, sE);
    scan_pass2<<<cgrid, 256>>>(sP, sE, h0, sC, hidden);
    scan_pass3_a<<<pgrid, 256>>>(gU, gF, gO, x, sC, Ah);   // h1 -> fp16 over A

    // Layer 2
    gemm_mma2<<<ggrid, 256, SMEM_NEED>>>(Ah, W2h, b2, gU, gF, gO);
    scan_pass1<<<pgrid, 256>>>(gU, gF, sP, sE);
    scan_pass2<<<cgrid, 256>>>(sP, sE, h0 + CHN, sC, hidden + CHN);
    scan_pass3_b<<<pgrid, 256>>>(gU, gF, gO, Ah, sC, h2);
}